// round 2
// baseline (speedup 1.0000x reference)
#include <cuda_runtime.h>
#include <cstddef>

#define N_NODES 50000
#define N_EDGES 800000
#define FEAT    128
#define HEADS   8
#define NEG_SLOPE 0.2f

typedef unsigned long long u64;

// ---------------- device scratch ---------------------------------------------
__device__ float g_feat_src[(size_t)N_NODES * FEAT];    // 25.6 MB
__device__ float g_feat_dst[(size_t)N_NODES * FEAT];    // 25.6 MB
__device__ float g_z[(size_t)N_NODES * HEADS];          // 1.6 MB

// ---------------- packed fp32x2 helpers --------------------------------------
__device__ __forceinline__ u64 pack_dup(float x) {
    u64 r;
    asm("mov.b64 %0, {%1,%1};" : "=l"(r) : "f"(x));
    return r;
}
__device__ __forceinline__ void fma2(u64& d, u64 a, u64 b) {
    asm("fma.rn.f32x2 %0, %1, %2, %0;" : "+l"(d) : "l"(a), "l"(b));
}
__device__ __forceinline__ float2 asf2(u64 v) {
    return *reinterpret_cast<float2*>(&v);
}

// ---------------- K0: zero accumulators --------------------------------------
__global__ void zero_kernel(float* __restrict__ out)
{
    int i = blockIdx.x * blockDim.x + threadIdx.x;
    if (i < N_NODES * FEAT) out[i] = 0.0f;
    if (i < N_NODES * HEADS) g_z[i] = 0.0f;
}

// ---------------- GEMM: C[M,128] = A[M,128] @ W[128,128]^T -------------------
// BM=BN=128, BK=16, 256 threads, 8x8 per thread, inner loop in packed f32x2.
// FUSED=true: instead of writing C, stage the tile in smem and run the
// per-edge GATv2 score + exp + scatter epilogue (warp per edge).
template<bool FUSED>
__global__ __launch_bounds__(256) void gemm_k(
    const float* __restrict__ A, const float* __restrict__ W,
    const float* __restrict__ bias, float* __restrict__ C, int M,
    const int* __restrict__ src, const int* __restrict__ dst,
    const float* __restrict__ attn, float* __restrict__ out)
{
    extern __shared__ float sbuf[];
    float (*As)[132] = (float(*)[132])sbuf;              // 16 x 132
    float (*Bs)[132] = (float(*)[132])(sbuf + 16 * 132); // 16 x 132

    const int tid = threadIdx.x;
    const int tx = tid & 15;
    const int ty = tid >> 4;
    const int bm = blockIdx.x * 128;

    u64 acc2[8][4];   // [row i][col-pair j]; pairs: (c0,c1)(c2,c3)(c4,c5)(c6,c7)
#pragma unroll
    for (int i = 0; i < 8; i++)
#pragma unroll
        for (int j = 0; j < 4; j++) acc2[i][j] = 0ull;

    for (int kt = 0; kt < 128; kt += 16) {
#pragma unroll
        for (int r = 0; r < 2; r++) {
            int idx = tid * 2 + r;          // 0..511
            int row = idx >> 2;             // 0..127
            int c4  = (idx & 3) << 2;       // 0,4,8,12
            float4 av = make_float4(0.f, 0.f, 0.f, 0.f);
            if (FUSED || bm + row < M)
                av = *(const float4*)(A + (size_t)(bm + row) * 128 + kt + c4);
            As[c4 + 0][row] = av.x; As[c4 + 1][row] = av.y;
            As[c4 + 2][row] = av.z; As[c4 + 3][row] = av.w;
            float4 wv = *(const float4*)(W + (size_t)row * 128 + kt + c4);
            Bs[c4 + 0][row] = wv.x; Bs[c4 + 1][row] = wv.y;
            Bs[c4 + 2][row] = wv.z; Bs[c4 + 3][row] = wv.w;
        }
        __syncthreads();

#pragma unroll
        for (int kk = 0; kk < 16; kk++) {
            float a[8];
            *(float4*)&a[0] = *(const float4*)&As[kk][ty * 4];
            *(float4*)&a[4] = *(const float4*)&As[kk][64 + ty * 4];
            ulonglong2 b01 = *(const ulonglong2*)&Bs[kk][tx * 4];
            ulonglong2 b23 = *(const ulonglong2*)&Bs[kk][64 + tx * 4];
#pragma unroll
            for (int i = 0; i < 8; i++) {
                u64 ap = pack_dup(a[i]);
                fma2(acc2[i][0], ap, b01.x);
                fma2(acc2[i][1], ap, b01.y);
                fma2(acc2[i][2], ap, b23.x);
                fma2(acc2[i][3], ap, b23.y);
            }
        }
        __syncthreads();
    }

    if (!FUSED) {
        // node projection epilogue: add bias, write C
        float bcol[8];
#pragma unroll
        for (int j = 0; j < 8; j++) {
            int col = (j < 4) ? (tx * 4 + j) : (64 + tx * 4 + (j - 4));
            bcol[j] = bias ? bias[col] : 0.0f;
        }
#pragma unroll
        for (int i = 0; i < 8; i++) {
            int row = (i < 4) ? (bm + ty * 4 + i) : (bm + 64 + ty * 4 + (i - 4));
            if (row < M) {
                float2 p0 = asf2(acc2[i][0]), p1 = asf2(acc2[i][1]);
                float2 p2 = asf2(acc2[i][2]), p3 = asf2(acc2[i][3]);
                float4 v0 = make_float4(p0.x + bcol[0], p0.y + bcol[1],
                                        p1.x + bcol[2], p1.y + bcol[3]);
                float4 v1 = make_float4(p2.x + bcol[4], p2.y + bcol[5],
                                        p3.x + bcol[6], p3.y + bcol[7]);
                *(float4*)(C + (size_t)row * 128 + tx * 4) = v0;
                *(float4*)(C + (size_t)row * 128 + 64 + tx * 4) = v1;
            }
        }
    } else {
        // ---- fused GATv2 edge epilogue ----
        // stage acc tile (feat_edge for 128 edges) into smem, reusing As/Bs space
        float (*Cs)[132] = (float(*)[132])sbuf;   // 128 x 132
#pragma unroll
        for (int i = 0; i < 8; i++) {
            int row = (i < 4) ? (ty * 4 + i) : (64 + ty * 4 + (i - 4));
            float2 p0 = asf2(acc2[i][0]), p1 = asf2(acc2[i][1]);
            float2 p2 = asf2(acc2[i][2]), p3 = asf2(acc2[i][3]);
            *(float4*)&Cs[row][tx * 4]      = make_float4(p0.x, p0.y, p1.x, p1.y);
            *(float4*)&Cs[row][64 + tx * 4] = make_float4(p2.x, p2.y, p3.x, p3.y);
        }
        __syncthreads();

        const int lane = tid & 31;
        const int w = tid >> 5;                   // 8 warps x 16 edges
        const float4 at = *(const float4*)(attn + lane * 4);

#pragma unroll 2
        for (int t = 0; t < 16; t++) {
            int el = w * 16 + t;
            int e  = bm + el;                     // N_EDGES % 128 == 0: no guard
            int s = __ldg(src + e);
            int d = __ldg(dst + e);

            float4 fe = *(const float4*)&Cs[el][lane * 4];
            float4 fs = *(const float4*)(g_feat_src + (size_t)s * FEAT + lane * 4);
            float4 fd = *(const float4*)(g_feat_dst + (size_t)d * FEAT + lane * 4);

            float t0 = fs.x + fd.x + fe.x;
            float t1 = fs.y + fd.y + fe.y;
            float t2 = fs.z + fd.z + fe.z;
            float t3 = fs.w + fd.w + fe.w;
            float l0 = (t0 >= 0.f) ? t0 : NEG_SLOPE * t0;
            float l1 = (t1 >= 0.f) ? t1 : NEG_SLOPE * t1;
            float l2 = (t2 >= 0.f) ? t2 : NEG_SLOPE * t2;
            float l3 = (t3 >= 0.f) ? t3 : NEG_SLOPE * t3;

            float p = l0 * at.x + l1 * at.y + l2 * at.z + l3 * at.w;
            p += __shfl_xor_sync(0xffffffffu, p, 1);
            p += __shfl_xor_sync(0xffffffffu, p, 2);

            float ex = __expf(p);

            if ((lane & 3) == 0)
                atomicAdd(&g_z[(size_t)d * HEADS + (lane >> 2)], ex);

            float mx = (fs.x + fe.x) * ex;
            float my = (fs.y + fe.y) * ex;
            float mz = (fs.z + fe.z) * ex;
            float mw = (fs.w + fe.w) * ex;

            float* op = out + (size_t)d * FEAT + lane * 4;
            asm volatile("red.global.add.v4.f32 [%0], {%1,%2,%3,%4};"
                         :: "l"(op), "f"(mx), "f"(my), "f"(mz), "f"(mw)
                         : "memory");
        }
    }
}

// ---------------- K3: finalize out = relu(acc / z) ---------------------------
__global__ void finalize(float* __restrict__ out)
{
    int i = blockIdx.x * blockDim.x + threadIdx.x;   // one per float4
    if (i >= N_NODES * 32) return;
    int n = i >> 5;
    int q = i & 31;
    int h = q >> 2;
    float z = g_z[(size_t)n * HEADS + h];
    float inv = (z > 0.f) ? (1.f / z) : 0.f;
    float4 v = *(float4*)(out + (size_t)n * FEAT + q * 4);
    v.x = fmaxf(v.x * inv, 0.f);
    v.y = fmaxf(v.y * inv, 0.f);
    v.z = fmaxf(v.z * inv, 0.f);
    v.w = fmaxf(v.w * inv, 0.f);
    *(float4*)(out + (size_t)n * FEAT + q * 4) = v;
}

// ---------------- launch -----------------------------------------------------
extern "C" void kernel_launch(void* const* d_in, const int* in_sizes, int n_in,
                              void* d_out, int out_size)
{
    const float* x      = (const float*)d_in[0];
    const float* efeat  = (const float*)d_in[1];
    const int*   src    = (const int*)d_in[2];
    const int*   dst    = (const int*)d_in[3];
    const float* W_src  = (const float*)d_in[4];
    const float* b_src  = (const float*)d_in[5];
    const float* W_dst  = (const float*)d_in[6];
    const float* b_dst  = (const float*)d_in[7];
    const float* W_edge = (const float*)d_in[8];
    const float* attn   = (const float*)d_in[9];
    float* out = (float*)d_out;

    float *p_fsrc = nullptr, *p_fdst = nullptr;
    cudaGetSymbolAddress((void**)&p_fsrc, g_feat_src);
    cudaGetSymbolAddress((void**)&p_fdst, g_feat_dst);

    const int smem_node  = 2 * 16 * 132 * sizeof(float);     // 16.9 KB
    const int smem_fused = 128 * 132 * sizeof(float);        // 67.6 KB
    cudaFuncSetAttribute(gemm_k<true>,
                         cudaFuncAttributeMaxDynamicSharedMemorySize, smem_fused);

    // K0: zero d_out and g_z
    zero_kernel<<<(N_NODES * FEAT + 255) / 256, 256>>>(out);

    // node projections
    int nb_node = (N_NODES + 127) / 128;   // 391
    gemm_k<false><<<nb_node, 256, smem_node>>>(x, W_src, b_src, p_fsrc, N_NODES,
                                               nullptr, nullptr, nullptr, nullptr);
    gemm_k<false><<<nb_node, 256, smem_node>>>(x, W_dst, b_dst, p_fdst, N_NODES,
                                               nullptr, nullptr, nullptr, nullptr);

    // fused edge projection + score + scatter
    int nb_edge = N_EDGES / 128;           // 6250
    gemm_k<true><<<nb_edge, 256, smem_fused>>>(efeat, W_edge, nullptr, nullptr,
                                               N_EDGES, src, dst, attn, out);

    // normalize + relu
    finalize<<<(N_NODES * 32 + 255) / 256, 256>>>(out);
}

// round 4
// speedup vs baseline: 2.3396x; 2.3396x over previous
#include <cuda_runtime.h>
#include <cuda_bf16.h>
#include <cstdint>
#include <cstddef>

#define N_NODES 50000
#define N_EDGES 800000
#define FEAT    128
#define HEADS   8
#define NEG_SLOPE 0.2f

typedef unsigned long long u64;
typedef unsigned int u32;

// ---------------- device scratch ---------------------------------------------
__device__ float g_feat_src[(size_t)N_NODES * FEAT];    // 25.6 MB
__device__ float g_feat_dst[(size_t)N_NODES * FEAT];    // 25.6 MB
__device__ float g_z[(size_t)N_NODES * HEADS];          // 1.6 MB
// W splits: [3 weights][hi/lo][128*128] bf16
__device__ __nv_bfloat16 g_wsplit[3 * 2 * FEAT * FEAT];

// ---------------- smem map ----------------------------------------------------
// bf16 tiles, padded row stride 72 (kc=64 + 8): 128 rows each.
#define PAD_K   72
#define SA_H    0
#define SA_L    18432
#define SW_H    36864
#define SW_L    55296
#define SMEM_BYTES 73728
// epilogue D tile (128 x 132 f32 = 67584 B) overlays the smem arena.

// ---------------- helpers -----------------------------------------------------
__device__ __forceinline__ u32 smem_u32(const void* p) {
    u32 a;
    asm("{ .reg .u64 t; cvta.to.shared.u64 t, %1; cvt.u32.u64 %0, t; }"
        : "=r"(a) : "l"(p));
    return a;
}
__device__ __forceinline__ void ldsm4(u32& r0, u32& r1, u32& r2, u32& r3, u32 addr) {
    asm volatile("ldmatrix.sync.aligned.m8n8.x4.shared.b16 {%0,%1,%2,%3}, [%4];"
                 : "=r"(r0), "=r"(r1), "=r"(r2), "=r"(r3) : "r"(addr));
}
__device__ __forceinline__ void mma_bf16(float* c, const u32* a, u32 b0, u32 b1) {
    asm volatile("mma.sync.aligned.m16n8k16.row.col.f32.bf16.bf16.f32 "
                 "{%0,%1,%2,%3}, {%4,%5,%6,%7}, {%8,%9}, {%0,%1,%2,%3};"
                 : "+f"(c[0]), "+f"(c[1]), "+f"(c[2]), "+f"(c[3])
                 : "r"(a[0]), "r"(a[1]), "r"(a[2]), "r"(a[3]), "r"(b0), "r"(b1));
}
// fp32x4 -> (hi bf16x4, lo bf16x4)
__device__ __forceinline__ void cvt_hilo(float4 v, u64& hi, u64& lo) {
    u32 h01, h23;
    asm("cvt.rn.bf16x2.f32 %0, %1, %2;" : "=r"(h01) : "f"(v.y), "f"(v.x));
    asm("cvt.rn.bf16x2.f32 %0, %1, %2;" : "=r"(h23) : "f"(v.w), "f"(v.z));
    float f0 = __uint_as_float(h01 << 16);
    float f1 = __uint_as_float(h01 & 0xffff0000u);
    float f2 = __uint_as_float(h23 << 16);
    float f3 = __uint_as_float(h23 & 0xffff0000u);
    u32 l01, l23;
    asm("cvt.rn.bf16x2.f32 %0, %1, %2;" : "=r"(l01) : "f"(v.y - f1), "f"(v.x - f0));
    asm("cvt.rn.bf16x2.f32 %0, %1, %2;" : "=r"(l23) : "f"(v.w - f3), "f"(v.z - f2));
    hi = (u64)h01 | ((u64)h23 << 32);
    lo = (u64)l01 | ((u64)l23 << 32);
}

// ---------------- K0: zero ----------------------------------------------------
__global__ void zero_kernel(float* __restrict__ out)
{
    int i = blockIdx.x * blockDim.x + threadIdx.x;
    if (i < N_NODES * FEAT) out[i] = 0.0f;
    if (i < N_NODES * HEADS) g_z[i] = 0.0f;
}

// ---------------- K-prep: split the three weight matrices into bf16 hi/lo ----
__global__ void prep_w(const float* __restrict__ Ws, const float* __restrict__ Wd,
                       const float* __restrict__ We)
{
    int idx = blockIdx.x * blockDim.x + threadIdx.x;   // 0 .. 3*16384-1
    if (idx >= 3 * FEAT * FEAT) return;
    int w = idx / (FEAT * FEAT);
    int i = idx - w * (FEAT * FEAT);
    const float* srcp = (w == 0) ? Ws : (w == 1) ? Wd : We;
    float v = srcp[i];
    __nv_bfloat16 hi = __float2bfloat16_rn(v);
    __nv_bfloat16 lo = __float2bfloat16_rn(v - __bfloat162float(hi));
    g_wsplit[(w * 2 + 0) * FEAT * FEAT + i] = hi;
    g_wsplit[(w * 2 + 1) * FEAT * FEAT + i] = lo;
}

// ---------------- MMA GEMM: D[128,128] = A @ W^T (3-term bf16 split) ---------
// 8 warps, warp tile 32x64 (warp_m = wid>>1, warp_n = wid&1), K chunks of 64.
// FUSED=false: node projection (bias + guarded store). FUSED=true: GATv2 edge
// epilogue from smem-staged D.
template<bool FUSED>
__global__ __launch_bounds__(256, 2) void mma_gemm(
    const float* __restrict__ A,
    const __nv_bfloat16* __restrict__ Wh, const __nv_bfloat16* __restrict__ Wl,
    const float* __restrict__ bias, float* __restrict__ C, int M,
    const int* __restrict__ src, const int* __restrict__ dst,
    const float* __restrict__ attn, float* __restrict__ out)
{
    extern __shared__ char smem[];
    const u32 sbase = smem_u32(smem);
    float* sf = (float*)smem;
    const int tid = threadIdx.x;
    const int lane = tid & 31;
    const int wid = tid >> 5;
    const int warp_m = wid >> 1;       // 0..3 (rows of 32)
    const int warp_n = wid & 1;        // 0..1 (cols of 64)
    const int bm = blockIdx.x * 128;

    float acc[2][8][4];
#pragma unroll
    for (int mi = 0; mi < 2; mi++)
#pragma unroll
        for (int ng = 0; ng < 8; ng++)
#pragma unroll
            for (int j = 0; j < 4; j++) acc[mi][ng][j] = 0.0f;

    // per-lane ldmatrix base offsets (bytes) within a tile
    const int a_row = warp_m * 32 + ((lane >> 3) & 1) * 8 + (lane & 7);
    const int a_col = (lane >> 4) * 8;
    const u32 a_base = (u32)(a_row * PAD_K + a_col) * 2;
    const int b_row = warp_n * 64 + (lane >> 4) * 8 + (lane & 7);
    const int b_col = ((lane >> 3) & 1) * 8;
    const u32 b_base = (u32)(b_row * PAD_K + b_col) * 2;

    for (int c = 0; c < 2; c++) {
        const int k0 = c * 64;
        // ---- load A chunk (128 x 64 f32), split to bf16 hi/lo ----
#pragma unroll
        for (int it = 0; it < 8; it++) {
            int idx = it * 256 + tid;        // 0..2047 float4s
            int row = idx >> 4;
            int c4  = (idx & 15) << 2;
            float4 av = make_float4(0.f, 0.f, 0.f, 0.f);
            if (FUSED || bm + row < M)
                av = *(const float4*)(A + (size_t)(bm + row) * FEAT + k0 + c4);
            u64 hi, lo;
            cvt_hilo(av, hi, lo);
            u32 soff = (u32)(row * PAD_K + c4) * 2;
            *(u64*)(smem + SA_H + soff) = hi;
            *(u64*)(smem + SA_L + soff) = lo;
        }
        // ---- load W chunk (128 n-rows x 64 k) hi/lo bf16 ----
#pragma unroll
        for (int it = 0; it < 4; it++) {
            int idx = it * 256 + tid;        // 0..1023 x 8bf16
            int row = idx >> 3;
            int c8  = (idx & 7) << 3;
            uint4 wh = *(const uint4*)(Wh + (size_t)row * FEAT + k0 + c8);
            uint4 wl = *(const uint4*)(Wl + (size_t)row * FEAT + k0 + c8);
            u32 soff = (u32)(row * PAD_K + c8) * 2;
            *(uint4*)(smem + SW_H + soff) = wh;
            *(uint4*)(smem + SW_L + soff) = wl;
        }
        __syncthreads();

        // ---- 4 k-steps of m16n8k16 ----
#pragma unroll
        for (int ks = 0; ks < 4; ks++) {
            const u32 koff = (u32)(ks * 16) * 2;
            u32 ah[2][4], al[2][4];
            ldsm4(ah[0][0], ah[0][1], ah[0][2], ah[0][3], sbase + SA_H + a_base + koff);
            ldsm4(ah[1][0], ah[1][1], ah[1][2], ah[1][3],
                  sbase + SA_H + a_base + (u32)(16 * PAD_K) * 2 + koff);
            ldsm4(al[0][0], al[0][1], al[0][2], al[0][3], sbase + SA_L + a_base + koff);
            ldsm4(al[1][0], al[1][1], al[1][2], al[1][3],
                  sbase + SA_L + a_base + (u32)(16 * PAD_K) * 2 + koff);
#pragma unroll
            for (int p = 0; p < 4; p++) {
                const u32 poff = (u32)(p * 16 * PAD_K) * 2 + koff;
                u32 bh[4], bl[4];
                ldsm4(bh[0], bh[1], bh[2], bh[3], sbase + SW_H + b_base + poff);
                ldsm4(bl[0], bl[1], bl[2], bl[3], sbase + SW_L + b_base + poff);
                int g0 = 2 * p, g1 = 2 * p + 1;
                mma_bf16(acc[0][g0], ah[0], bh[0], bh[1]);
                mma_bf16(acc[1][g0], ah[1], bh[0], bh[1]);
                mma_bf16(acc[0][g1], ah[0], bh[2], bh[3]);
                mma_bf16(acc[1][g1], ah[1], bh[2], bh[3]);
                mma_bf16(acc[0][g0], al[0], bh[0], bh[1]);
                mma_bf16(acc[1][g0], al[1], bh[0], bh[1]);
                mma_bf16(acc[0][g1], al[0], bh[2], bh[3]);
                mma_bf16(acc[1][g1], al[1], bh[2], bh[3]);
                mma_bf16(acc[0][g0], ah[0], bl[0], bl[1]);
                mma_bf16(acc[1][g0], ah[1], bl[0], bl[1]);
                mma_bf16(acc[0][g1], ah[0], bl[2], bl[3]);
                mma_bf16(acc[1][g1], ah[1], bl[2], bl[3]);
            }
        }
        __syncthreads();
    }

    // ---- stage D (128x128 f32, row stride 132) into smem ----
#pragma unroll
    for (int mi = 0; mi < 2; mi++) {
        int r0 = warp_m * 32 + mi * 16 + (lane >> 2);
        int cc = warp_n * 64 + (lane & 3) * 2;
#pragma unroll
        for (int ng = 0; ng < 8; ng++) {
            int col = cc + ng * 8;
            *(float2*)&sf[r0 * 132 + col] =
                make_float2(acc[mi][ng][0], acc[mi][ng][1]);
            *(float2*)&sf[(r0 + 8) * 132 + col] =
                make_float2(acc[mi][ng][2], acc[mi][ng][3]);
        }
    }
    __syncthreads();

    if (!FUSED) {
        float4 b4 = make_float4(0.f, 0.f, 0.f, 0.f);
        if (bias) b4 = *(const float4*)(bias + (tid & 31) * 4);
#pragma unroll 4
        for (int i = 0; i < 16; i++) {
            int row = i * 8 + (tid >> 5);
            int gr = bm + row;
            if (gr < M) {
                float4 v = *(const float4*)&sf[row * 132 + (tid & 31) * 4];
                v.x += b4.x; v.y += b4.y; v.z += b4.z; v.w += b4.w;
                *(float4*)(C + (size_t)gr * FEAT + (tid & 31) * 4) = v;
            }
        }
    } else {
        // ---- fused GATv2 edge epilogue: warp per edge, 16 edges/warp ----
        const float4 at = *(const float4*)(attn + lane * 4);
#pragma unroll 2
        for (int t = 0; t < 16; t++) {
            int el = wid * 16 + t;
            int e  = bm + el;                 // N_EDGES % 128 == 0
            int s = __ldg(src + e);
            int d = __ldg(dst + e);

            float4 fe = *(const float4*)&sf[el * 132 + lane * 4];
            float4 fs = *(const float4*)(g_feat_src + (size_t)s * FEAT + lane * 4);
            float4 fd = *(const float4*)(g_feat_dst + (size_t)d * FEAT + lane * 4);

            float t0 = fs.x + fd.x + fe.x;
            float t1 = fs.y + fd.y + fe.y;
            float t2 = fs.z + fd.z + fe.z;
            float t3 = fs.w + fd.w + fe.w;
            float l0 = (t0 >= 0.f) ? t0 : NEG_SLOPE * t0;
            float l1 = (t1 >= 0.f) ? t1 : NEG_SLOPE * t1;
            float l2 = (t2 >= 0.f) ? t2 : NEG_SLOPE * t2;
            float l3 = (t3 >= 0.f) ? t3 : NEG_SLOPE * t3;

            float p = l0 * at.x + l1 * at.y + l2 * at.z + l3 * at.w;
            p += __shfl_xor_sync(0xffffffffu, p, 1);
            p += __shfl_xor_sync(0xffffffffu, p, 2);

            float ex = __expf(p);

            if ((lane & 3) == 0)
                atomicAdd(&g_z[(size_t)d * HEADS + (lane >> 2)], ex);

            float mx = (fs.x + fe.x) * ex;
            float my = (fs.y + fe.y) * ex;
            float mz = (fs.z + fe.z) * ex;
            float mw = (fs.w + fe.w) * ex;

            float* op = out + (size_t)d * FEAT + lane * 4;
            asm volatile("red.global.add.v4.f32 [%0], {%1,%2,%3,%4};"
                         :: "l"(op), "f"(mx), "f"(my), "f"(mz), "f"(mw)
                         : "memory");
        }
    }
}

// ---------------- K3: finalize out = relu(acc / z) ---------------------------
__global__ void finalize(float* __restrict__ out)
{
    int i = blockIdx.x * blockDim.x + threadIdx.x;
    if (i >= N_NODES * 32) return;
    int n = i >> 5;
    int q = i & 31;
    int h = q >> 2;
    float z = g_z[(size_t)n * HEADS + h];
    float inv = (z > 0.f) ? (1.f / z) : 0.f;
    float4 v = *(float4*)(out + (size_t)n * FEAT + q * 4);
    v.x = fmaxf(v.x * inv, 0.f);
    v.y = fmaxf(v.y * inv, 0.f);
    v.z = fmaxf(v.z * inv, 0.f);
    v.w = fmaxf(v.w * inv, 0.f);
    *(float4*)(out + (size_t)n * FEAT + q * 4) = v;
}

// ---------------- launch -----------------------------------------------------
extern "C" void kernel_launch(void* const* d_in, const int* in_sizes, int n_in,
                              void* d_out, int out_size)
{
    const float* x      = (const float*)d_in[0];
    const float* efeat  = (const float*)d_in[1];
    const int*   src    = (const int*)d_in[2];
    const int*   dst    = (const int*)d_in[3];
    const float* W_src  = (const float*)d_in[4];
    const float* b_src  = (const float*)d_in[5];
    const float* W_dst  = (const float*)d_in[6];
    const float* b_dst  = (const float*)d_in[7];
    const float* W_edge = (const float*)d_in[8];
    const float* attn   = (const float*)d_in[9];
    float* out = (float*)d_out;

    float *p_fsrc = nullptr, *p_fdst = nullptr;
    __nv_bfloat16* p_w = nullptr;
    cudaGetSymbolAddress((void**)&p_fsrc, g_feat_src);
    cudaGetSymbolAddress((void**)&p_fdst, g_feat_dst);
    cudaGetSymbolAddress((void**)&p_w, g_wsplit);

    cudaFuncSetAttribute(mma_gemm<false>,
                         cudaFuncAttributeMaxDynamicSharedMemorySize, SMEM_BYTES);
    cudaFuncSetAttribute(mma_gemm<true>,
                         cudaFuncAttributeMaxDynamicSharedMemorySize, SMEM_BYTES);

    // zero + weight split prep
    zero_kernel<<<(N_NODES * FEAT + 255) / 256, 256>>>(out);
    prep_w<<<(3 * FEAT * FEAT + 255) / 256, 256>>>(W_src, W_dst, W_edge);

    const int WSZ = FEAT * FEAT;
    // node projections
    int nb_node = (N_NODES + 127) / 128;   // 391
    mma_gemm<false><<<nb_node, 256, SMEM_BYTES>>>(
        x, p_w + 0 * WSZ, p_w + 1 * WSZ, b_src, p_fsrc, N_NODES,
        nullptr, nullptr, nullptr, nullptr);
    mma_gemm<false><<<nb_node, 256, SMEM_BYTES>>>(
        x, p_w + 2 * WSZ, p_w + 3 * WSZ, b_dst, p_fdst, N_NODES,
        nullptr, nullptr, nullptr, nullptr);

    // fused edge projection + score + scatter
    int nb_edge = N_EDGES / 128;           // 6250
    mma_gemm<true><<<nb_edge, 256, SMEM_BYTES>>>(
        efeat, p_w + 4 * WSZ, p_w + 5 * WSZ, nullptr, nullptr, N_EDGES,
        src, dst, attn, out);

    // normalize + relu
    finalize<<<(N_NODES * 32 + 255) / 256, 256>>>(out);
}

// round 6
// speedup vs baseline: 2.6241x; 1.1216x over previous
#include <cuda_runtime.h>
#include <cuda_fp16.h>
#include <cstdint>
#include <cstddef>

#define N_NODES 50000
#define N_EDGES 800000
#define FEAT    128
#define HEADS   8
#define NEG_SLOPE 0.2f

typedef unsigned long long u64;
typedef unsigned int u32;

// ---------------- device scratch ---------------------------------------------
__device__ float g_feat_src[(size_t)N_NODES * FEAT];    // 25.6 MB
__device__ float g_feat_dst[(size_t)N_NODES * FEAT];    // 25.6 MB
__device__ float g_z[(size_t)N_NODES * HEADS];          // 1.6 MB
// W splits: [3 weights][hi/lo][128*128] fp16
__device__ __half g_wsplit[3 * 2 * FEAT * FEAT];

// ---------------- smem map ----------------------------------------------------
// fp16 tiles, padded row stride 72 (kc=64 + 8): 128 rows each (18432 B).
#define PAD_K   72
#define SA      0
#define SW_H    18432
#define SW_L    36864
#define SMEM_BYTES 67584     // D overlay: 128 x 132 f32

// ---------------- helpers -----------------------------------------------------
__device__ __forceinline__ u32 smem_u32(const void* p) {
    u32 a;
    asm("{ .reg .u64 t; cvta.to.shared.u64 t, %1; cvt.u32.u64 %0, t; }"
        : "=r"(a) : "l"(p));
    return a;
}
__device__ __forceinline__ void ldsm4(u32& r0, u32& r1, u32& r2, u32& r3, u32 addr) {
    asm volatile("ldmatrix.sync.aligned.m8n8.x4.shared.b16 {%0,%1,%2,%3}, [%4];"
                 : "=r"(r0), "=r"(r1), "=r"(r2), "=r"(r3) : "r"(addr));
}
__device__ __forceinline__ void mma_f16(float* c, const u32* a, u32 b0, u32 b1) {
    asm volatile("mma.sync.aligned.m16n8k16.row.col.f32.f16.f16.f32 "
                 "{%0,%1,%2,%3}, {%4,%5,%6,%7}, {%8,%9}, {%0,%1,%2,%3};"
                 : "+f"(c[0]), "+f"(c[1]), "+f"(c[2]), "+f"(c[3])
                 : "r"(a[0]), "r"(a[1]), "r"(a[2]), "r"(a[3]), "r"(b0), "r"(b1));
}
// fp32x4 -> fp16x4 (packed u64)
__device__ __forceinline__ u64 cvt4_f16(float4 v) {
    u32 p01, p23;
    asm("cvt.rn.f16x2.f32 %0, %1, %2;" : "=r"(p01) : "f"(v.y), "f"(v.x));
    asm("cvt.rn.f16x2.f32 %0, %1, %2;" : "=r"(p23) : "f"(v.w), "f"(v.z));
    return (u64)p01 | ((u64)p23 << 32);
}

// ---------------- K0: zero ----------------------------------------------------
__global__ void zero_kernel(float* __restrict__ out)
{
    int i = blockIdx.x * blockDim.x + threadIdx.x;
    if (i < N_NODES * FEAT) out[i] = 0.0f;
    if (i < N_NODES * HEADS) g_z[i] = 0.0f;
}

// ---------------- K-prep: split the three weight matrices into fp16 hi/lo ----
__global__ void prep_w(const float* __restrict__ Ws, const float* __restrict__ Wd,
                       const float* __restrict__ We)
{
    int idx = blockIdx.x * blockDim.x + threadIdx.x;   // 0 .. 3*16384-1
    if (idx >= 3 * FEAT * FEAT) return;
    int w = idx / (FEAT * FEAT);
    int i = idx - w * (FEAT * FEAT);
    const float* srcp = (w == 0) ? Ws : (w == 1) ? Wd : We;
    float v = srcp[i];
    __half hi = __float2half_rn(v);
    __half lo = __float2half_rn(v - __half2float(hi));
    g_wsplit[(w * 2 + 0) * FEAT * FEAT + i] = hi;
    g_wsplit[(w * 2 + 1) * FEAT * FEAT + i] = lo;
}

// ---------------- MMA GEMM: D[128,128] = A @ W^T (2-term fp16 split) ---------
// A single fp16; W = Wh + Wl. 8 warps, warp tile 32x64, K chunks of 64.
// FUSED=false: node projection (bias + guarded store). FUSED=true: GATv2 edge
// epilogue from smem-staged D.
template<bool FUSED>
__global__ __launch_bounds__(256, 2) void mma_gemm(
    const float* __restrict__ A,
    const __half* __restrict__ Wh, const __half* __restrict__ Wl,
    const float* __restrict__ bias, float* __restrict__ C, int M,
    const int* __restrict__ src, const int* __restrict__ dst,
    const float* __restrict__ attn, float* __restrict__ out)
{
    extern __shared__ char smem[];
    const u32 sbase = smem_u32(smem);
    float* sf = (float*)smem;
    const int tid = threadIdx.x;
    const int lane = tid & 31;
    const int wid = tid >> 5;
    const int warp_m = wid >> 1;       // 0..3 (rows of 32)
    const int warp_n = wid & 1;        // 0..1 (cols of 64)
    const int bm = blockIdx.x * 128;

    // preload this warp's 16 (src,dst) pairs into lanes 0..15 (fused only)
    int s_pre = 0, d_pre = 0;
    if (FUSED && lane < 16) {
        s_pre = __ldg(src + bm + wid * 16 + lane);
        d_pre = __ldg(dst + bm + wid * 16 + lane);
    }

    float acc[2][8][4];
#pragma unroll
    for (int mi = 0; mi < 2; mi++)
#pragma unroll
        for (int ng = 0; ng < 8; ng++)
#pragma unroll
            for (int j = 0; j < 4; j++) acc[mi][ng][j] = 0.0f;

    // per-lane ldmatrix base offsets (bytes) within a tile
    const int a_row = warp_m * 32 + ((lane >> 3) & 1) * 8 + (lane & 7);
    const int a_col = (lane >> 4) * 8;
    const u32 a_base = (u32)(a_row * PAD_K + a_col) * 2;
    const int b_row = warp_n * 64 + (lane >> 4) * 8 + (lane & 7);
    const int b_col = ((lane >> 3) & 1) * 8;
    const u32 b_base = (u32)(b_row * PAD_K + b_col) * 2;

    for (int c = 0; c < 2; c++) {
        const int k0 = c * 64;
        // ---- load A chunk (128 x 64 f32) -> fp16 smem ----
#pragma unroll
        for (int it = 0; it < 8; it++) {
            int idx = it * 256 + tid;        // 0..2047 float4s
            int row = idx >> 4;
            int c4  = (idx & 15) << 2;
            float4 av = make_float4(0.f, 0.f, 0.f, 0.f);
            if (FUSED || bm + row < M)
                av = *(const float4*)(A + (size_t)(bm + row) * FEAT + k0 + c4);
            *(u64*)(smem + SA + (u32)(row * PAD_K + c4) * 2) = cvt4_f16(av);
        }
        // ---- load W chunk (128 n-rows x 64 k) hi/lo fp16 ----
#pragma unroll
        for (int it = 0; it < 4; it++) {
            int idx = it * 256 + tid;        // 0..1023 x 8 halfs
            int row = idx >> 3;
            int c8  = (idx & 7) << 3;
            uint4 wh = *(const uint4*)(Wh + (size_t)row * FEAT + k0 + c8);
            uint4 wl = *(const uint4*)(Wl + (size_t)row * FEAT + k0 + c8);
            u32 soff = (u32)(row * PAD_K + c8) * 2;
            *(uint4*)(smem + SW_H + soff) = wh;
            *(uint4*)(smem + SW_L + soff) = wl;
        }
        __syncthreads();

        // ---- 4 k-steps of m16n8k16 ----
#pragma unroll
        for (int ks = 0; ks < 4; ks++) {
            const u32 koff = (u32)(ks * 16) * 2;
            u32 ah[2][4];
            ldsm4(ah[0][0], ah[0][1], ah[0][2], ah[0][3], sbase + SA + a_base + koff);
            ldsm4(ah[1][0], ah[1][1], ah[1][2], ah[1][3],
                  sbase + SA + a_base + (u32)(16 * PAD_K) * 2 + koff);
#pragma unroll
            for (int p = 0; p < 4; p++) {
                const u32 poff = (u32)(p * 16 * PAD_K) * 2 + koff;
                u32 bh[4], bl[4];
                ldsm4(bh[0], bh[1], bh[2], bh[3], sbase + SW_H + b_base + poff);
                ldsm4(bl[0], bl[1], bl[2], bl[3], sbase + SW_L + b_base + poff);
                int g0 = 2 * p, g1 = 2 * p + 1;
                mma_f16(acc[0][g0], ah[0], bh[0], bh[1]);
                mma_f16(acc[1][g0], ah[1], bh[0], bh[1]);
                mma_f16(acc[0][g1], ah[0], bh[2], bh[3]);
                mma_f16(acc[1][g1], ah[1], bh[2], bh[3]);
                mma_f16(acc[0][g0], ah[0], bl[0], bl[1]);
                mma_f16(acc[1][g0], ah[1], bl[0], bl[1]);
                mma_f16(acc[0][g1], ah[0], bl[2], bl[3]);
                mma_f16(acc[1][g1], ah[1], bl[2], bl[3]);
            }
        }
        __syncthreads();
    }

    // ---- stage D (128x128 f32, row stride 132) into smem ----
#pragma unroll
    for (int mi = 0; mi < 2; mi++) {
        int r0 = warp_m * 32 + mi * 16 + (lane >> 2);
        int cc = warp_n * 64 + (lane & 3) * 2;
#pragma unroll
        for (int ng = 0; ng < 8; ng++) {
            int col = cc + ng * 8;
            *(float2*)&sf[r0 * 132 + col] =
                make_float2(acc[mi][ng][0], acc[mi][ng][1]);
            *(float2*)&sf[(r0 + 8) * 132 + col] =
                make_float2(acc[mi][ng][2], acc[mi][ng][3]);
        }
    }
    __syncthreads();

    if (!FUSED) {
        float4 b4 = make_float4(0.f, 0.f, 0.f, 0.f);
        if (bias) b4 = *(const float4*)(bias + (tid & 31) * 4);
#pragma unroll 4
        for (int i = 0; i < 16; i++) {
            int row = i * 8 + (tid >> 5);
            int gr = bm + row;
            if (gr < M) {
                float4 v = *(const float4*)&sf[row * 132 + (tid & 31) * 4];
                v.x += b4.x; v.y += b4.y; v.z += b4.z; v.w += b4.w;
                *(float4*)(C + (size_t)gr * FEAT + (tid & 31) * 4) = v;
            }
        }
    } else {
        // ---- fused GATv2 edge epilogue: warp per edge, 16 edges/warp ----
        const float4 at = *(const float4*)(attn + lane * 4);
#pragma unroll 4
        for (int t = 0; t < 16; t++) {
            int el = wid * 16 + t;
            int s = __shfl_sync(0xffffffffu, s_pre, t);
            int d = __shfl_sync(0xffffffffu, d_pre, t);

            float4 fe = *(const float4*)&sf[el * 132 + lane * 4];
            float4 fs = *(const float4*)(g_feat_src + (size_t)s * FEAT + lane * 4);
            float4 fd = *(const float4*)(g_feat_dst + (size_t)d * FEAT + lane * 4);

            float t0 = fs.x + fd.x + fe.x;
            float t1 = fs.y + fd.y + fe.y;
            float t2 = fs.z + fd.z + fe.z;
            float t3 = fs.w + fd.w + fe.w;
            float l0 = (t0 >= 0.f) ? t0 : NEG_SLOPE * t0;
            float l1 = (t1 >= 0.f) ? t1 : NEG_SLOPE * t1;
            float l2 = (t2 >= 0.f) ? t2 : NEG_SLOPE * t2;
            float l3 = (t3 >= 0.f) ? t3 : NEG_SLOPE * t3;

            float p = l0 * at.x + l1 * at.y + l2 * at.z + l3 * at.w;
            p += __shfl_xor_sync(0xffffffffu, p, 1);
            p += __shfl_xor_sync(0xffffffffu, p, 2);

            float ex = __expf(p);

            if ((lane & 3) == 0)
                atomicAdd(&g_z[(size_t)d * HEADS + (lane >> 2)], ex);

            float mx = (fs.x + fe.x) * ex;
            float my = (fs.y + fe.y) * ex;
            float mz = (fs.z + fe.z) * ex;
            float mw = (fs.w + fe.w) * ex;

            float* op = out + (size_t)d * FEAT + lane * 4;
            asm volatile("red.global.add.v4.f32 [%0], {%1,%2,%3,%4};"
                         :: "l"(op), "f"(mx), "f"(my), "f"(mz), "f"(mw)
                         : "memory");
        }
    }
}

// ---------------- K3: finalize out = relu(acc / z) ---------------------------
__global__ void finalize(float* __restrict__ out)
{
    int i = blockIdx.x * blockDim.x + threadIdx.x;
    if (i >= N_NODES * 32) return;
    int n = i >> 5;
    int q = i & 31;
    int h = q >> 2;
    float z = g_z[(size_t)n * HEADS + h];
    float inv = (z > 0.f) ? (1.f / z) : 0.f;
    float4 v = *(float4*)(out + (size_t)n * FEAT + q * 4);
    v.x = fmaxf(v.x * inv, 0.f);
    v.y = fmaxf(v.y * inv, 0.f);
    v.z = fmaxf(v.z * inv, 0.f);
    v.w = fmaxf(v.w * inv, 0.f);
    *(float4*)(out + (size_t)n * FEAT + q * 4) = v;
}

// ---------------- launch -----------------------------------------------------
extern "C" void kernel_launch(void* const* d_in, const int* in_sizes, int n_in,
                              void* d_out, int out_size)
{
    const float* x      = (const float*)d_in[0];
    const float* efeat  = (const float*)d_in[1];
    const int*   src    = (const int*)d_in[2];
    const int*   dst    = (const int*)d_in[3];
    const float* W_src  = (const float*)d_in[4];
    const float* b_src  = (const float*)d_in[5];
    const float* W_dst  = (const float*)d_in[6];
    const float* b_dst  = (const float*)d_in[7];
    const float* W_edge = (const float*)d_in[8];
    const float* attn   = (const float*)d_in[9];
    float* out = (float*)d_out;

    float *p_fsrc = nullptr, *p_fdst = nullptr;
    __half* p_w = nullptr;
    cudaGetSymbolAddress((void**)&p_fsrc, g_feat_src);
    cudaGetSymbolAddress((void**)&p_fdst, g_feat_dst);
    cudaGetSymbolAddress((void**)&p_w, g_wsplit);

    cudaFuncSetAttribute(mma_gemm<false>,
                         cudaFuncAttributeMaxDynamicSharedMemorySize, SMEM_BYTES);
    cudaFuncSetAttribute(mma_gemm<true>,
                         cudaFuncAttributeMaxDynamicSharedMemorySize, SMEM_BYTES);

    // zero + weight split prep
    zero_kernel<<<(N_NODES * FEAT + 255) / 256, 256>>>(out);
    prep_w<<<(3 * FEAT * FEAT + 255) / 256, 256>>>(W_src, W_dst, W_edge);

    const int WSZ = FEAT * FEAT;
    // node projections
    int nb_node = (N_NODES + 127) / 128;   // 391
    mma_gemm<false><<<nb_node, 256, SMEM_BYTES>>>(
        x, p_w + 0 * WSZ, p_w + 1 * WSZ, b_src, p_fsrc, N_NODES,
        nullptr, nullptr, nullptr, nullptr);
    mma_gemm<false><<<nb_node, 256, SMEM_BYTES>>>(
        x, p_w + 2 * WSZ, p_w + 3 * WSZ, b_dst, p_fdst, N_NODES,
        nullptr, nullptr, nullptr, nullptr);

    // fused edge projection + score + scatter
    int nb_edge = N_EDGES / 128;           // 6250
    mma_gemm<true><<<nb_edge, 256, SMEM_BYTES>>>(
        efeat, p_w + 4 * WSZ, p_w + 5 * WSZ, nullptr, nullptr, N_EDGES,
        src, dst, attn, out);

    // normalize + relu
    finalize<<<(N_NODES * 32 + 255) / 256, 256>>>(out);
}

// round 8
// speedup vs baseline: 2.6913x; 1.0256x over previous
#include <cuda_runtime.h>
#include <cuda_fp16.h>
#include <cstdint>
#include <cstddef>

#define N_NODES 50000
#define N_EDGES 800000
#define FEAT    128
#define HEADS   8
#define NEG_SLOPE 0.2f

typedef unsigned long long u64;
typedef unsigned int u32;

// ---------------- device scratch ---------------------------------------------
__device__ float g_feat_src[(size_t)N_NODES * FEAT];    // 25.6 MB
__device__ float g_feat_dst[(size_t)N_NODES * FEAT];    // 25.6 MB
__device__ float g_z[(size_t)N_NODES * HEADS];          // 1.6 MB
// W splits: [3 weights][hi/lo][128*128] fp16
__device__ __half g_wsplit[3 * 2 * FEAT * FEAT];

// ---------------- smem map ----------------------------------------------------
// Full-K fp16 tiles, padded row stride 136 halfs (128 + 8): 128 rows = 34816 B.
#define PAD2    136
#define SA      0
#define SW_H    34816
#define SW_L    69632
#define SMEM_BYTES 104448
// D overlay (128 x 132 f32 = 67584 B) sits at SW_H (A tile stays intact).
#define SD      34816

// ---------------- helpers -----------------------------------------------------
__device__ __forceinline__ u32 smem_u32(const void* p) {
    u32 a;
    asm("{ .reg .u64 t; cvta.to.shared.u64 t, %1; cvt.u32.u64 %0, t; }"
        : "=r"(a) : "l"(p));
    return a;
}
__device__ __forceinline__ void ldsm4(u32& r0, u32& r1, u32& r2, u32& r3, u32 addr) {
    asm volatile("ldmatrix.sync.aligned.m8n8.x4.shared.b16 {%0,%1,%2,%3}, [%4];"
                 : "=r"(r0), "=r"(r1), "=r"(r2), "=r"(r3) : "r"(addr));
}
__device__ __forceinline__ void mma_f16(float* c, const u32* a, u32 b0, u32 b1) {
    asm volatile("mma.sync.aligned.m16n8k16.row.col.f32.f16.f16.f32 "
                 "{%0,%1,%2,%3}, {%4,%5,%6,%7}, {%8,%9}, {%0,%1,%2,%3};"
                 : "+f"(c[0]), "+f"(c[1]), "+f"(c[2]), "+f"(c[3])
                 : "r"(a[0]), "r"(a[1]), "r"(a[2]), "r"(a[3]), "r"(b0), "r"(b1));
}
__device__ __forceinline__ u64 cvt4_f16(float4 v) {
    u32 p01, p23;
    asm("cvt.rn.f16x2.f32 %0, %1, %2;" : "=r"(p01) : "f"(v.y), "f"(v.x));
    asm("cvt.rn.f16x2.f32 %0, %1, %2;" : "=r"(p23) : "f"(v.w), "f"(v.z));
    return (u64)p01 | ((u64)p23 << 32);
}
__device__ __forceinline__ void cp_async16(u32 saddr, const void* gaddr) {
    asm volatile("cp.async.cg.shared.global [%0], [%1], 16;"
                 :: "r"(saddr), "l"(gaddr) : "memory");
}
__device__ __forceinline__ void cp_async_wait_all() {
    asm volatile("cp.async.commit_group;" ::: "memory");
    asm volatile("cp.async.wait_group 0;" ::: "memory");
}

// ---------------- K0: zero (vectorized) ---------------------------------------
__global__ void zero_kernel(float4* __restrict__ out4)
{
    int i = blockIdx.x * blockDim.x + threadIdx.x;
    if (i < N_NODES * 32) out4[i] = make_float4(0.f, 0.f, 0.f, 0.f);
    if (i < N_NODES * HEADS / 4) ((float4*)g_z)[i] = make_float4(0.f, 0.f, 0.f, 0.f);
}

// ---------------- K-prep: split the three weight matrices into fp16 hi/lo ----
__global__ void prep_w(const float* __restrict__ Ws, const float* __restrict__ Wd,
                       const float* __restrict__ We)
{
    int idx = blockIdx.x * blockDim.x + threadIdx.x;
    if (idx >= 3 * FEAT * FEAT) return;
    int w = idx / (FEAT * FEAT);
    int i = idx - w * (FEAT * FEAT);
    const float* srcp = (w == 0) ? Ws : (w == 1) ? Wd : We;
    float v = srcp[i];
    __half hi = __float2half_rn(v);
    __half lo = __float2half_rn(v - __half2float(hi));
    g_wsplit[(w * 2 + 0) * FEAT * FEAT + i] = hi;
    g_wsplit[(w * 2 + 1) * FEAT * FEAT + i] = lo;
}

// ---------------- building blocks ---------------------------------------------
// load A tile (128x128 f32 -> fp16 smem @ SA), guarded by M
__device__ __forceinline__ void load_A(const float* __restrict__ A, char* smem,
                                       int bm, int M, int tid, bool guard)
{
#pragma unroll
    for (int it = 0; it < 16; it++) {
        int idx = it * 256 + tid;           // 0..4095 float4s
        int row = idx >> 5;                 // 0..127
        int c4  = (idx & 31) << 2;          // 0..124
        float4 av = make_float4(0.f, 0.f, 0.f, 0.f);
        if (!guard || bm + row < M)
            av = *(const float4*)(A + (size_t)(bm + row) * FEAT + c4);
        *(u64*)(smem + SA + (u32)(row * PAD2 + c4) * 2) = cvt4_f16(av);
    }
}
// cp.async W hi/lo tiles into SW_H/SW_L (128 rows x 128 cols fp16 each)
__device__ __forceinline__ void load_W(const __half* __restrict__ Wh,
                                       const __half* __restrict__ Wl,
                                       u32 sbase, int tid)
{
#pragma unroll
    for (int it = 0; it < 8; it++) {
        int idx = it * 256 + tid;           // 0..2047 uint4s per tile
        int row = idx >> 4;                 // 0..127
        int c8  = (idx & 15) << 3;          // 0..120
        u32 soff = (u32)(row * PAD2 + c8) * 2;
        cp_async16(sbase + SW_H + soff, Wh + (size_t)row * FEAT + c8);
        cp_async16(sbase + SW_L + soff, Wl + (size_t)row * FEAT + c8);
    }
    cp_async_wait_all();
}
// the 8-k-step MMA loop over full K
__device__ __forceinline__ void mma_loop(u32 sbase, u32 a_base, u32 b_base,
                                         float acc[2][8][4])
{
#pragma unroll
    for (int ks = 0; ks < 8; ks++) {
        const u32 koff = (u32)ks * 32;      // 16 halfs * 2 B
        u32 ah[2][4];
        ldsm4(ah[0][0], ah[0][1], ah[0][2], ah[0][3], sbase + SA + a_base + koff);
        ldsm4(ah[1][0], ah[1][1], ah[1][2], ah[1][3],
              sbase + SA + a_base + (u32)(16 * PAD2) * 2 + koff);
#pragma unroll
        for (int p = 0; p < 4; p++) {
            const u32 poff = (u32)(p * 16 * PAD2) * 2 + koff;
            u32 bh[4], bl[4];
            ldsm4(bh[0], bh[1], bh[2], bh[3], sbase + SW_H + b_base + poff);
            ldsm4(bl[0], bl[1], bl[2], bl[3], sbase + SW_L + b_base + poff);
            int g0 = 2 * p, g1 = 2 * p + 1;
            mma_f16(acc[0][g0], ah[0], bh[0], bh[1]);
            mma_f16(acc[1][g0], ah[1], bh[0], bh[1]);
            mma_f16(acc[0][g1], ah[0], bh[2], bh[3]);
            mma_f16(acc[1][g1], ah[1], bh[2], bh[3]);
            mma_f16(acc[0][g0], ah[0], bl[0], bl[1]);
            mma_f16(acc[1][g0], ah[1], bl[0], bl[1]);
            mma_f16(acc[0][g1], ah[0], bl[2], bl[3]);
            mma_f16(acc[1][g1], ah[1], bl[2], bl[3]);
        }
    }
}
// stage accumulators into the D overlay (rows x 132 f32 @ SD)
__device__ __forceinline__ void stage_D(float* sf, int warp_m, int warp_n, int lane,
                                        float acc[2][8][4])
{
#pragma unroll
    for (int mi = 0; mi < 2; mi++) {
        int r0 = warp_m * 32 + mi * 16 + (lane >> 2);
        int cc = warp_n * 64 + (lane & 3) * 2;
#pragma unroll
        for (int ng = 0; ng < 8; ng++) {
            int col = cc + ng * 8;
            *(float2*)&sf[r0 * 132 + col] =
                make_float2(acc[mi][ng][0], acc[mi][ng][1]);
            *(float2*)&sf[(r0 + 8) * 132 + col] =
                make_float2(acc[mi][ng][2], acc[mi][ng][3]);
        }
    }
}
__device__ __forceinline__ void zero_acc(float acc[2][8][4])
{
#pragma unroll
    for (int mi = 0; mi < 2; mi++)
#pragma unroll
        for (int ng = 0; ng < 8; ng++)
#pragma unroll
            for (int j = 0; j < 4; j++) acc[mi][ng][j] = 0.0f;
}
// store D (+bias) to C, coalesced, guarded
__device__ __forceinline__ void store_C(const float* sf, float* __restrict__ C,
                                        const float* __restrict__ bias,
                                        int bm, int M, int tid)
{
    float4 b4 = *(const float4*)(bias + (tid & 31) * 4);
#pragma unroll 4
    for (int i = 0; i < 16; i++) {
        int row = i * 8 + (tid >> 5);
        int gr = bm + row;
        if (gr < M) {
            float4 v = *(const float4*)&sf[row * 132 + (tid & 31) * 4];
            v.x += b4.x; v.y += b4.y; v.z += b4.z; v.w += b4.w;
            *(float4*)(C + (size_t)gr * FEAT + (tid & 31) * 4) = v;
        }
    }
}

// ---------------- node kernel: both projections, A tile loaded once ----------
__global__ __launch_bounds__(256, 2) void node_dual(
    const float* __restrict__ A,
    const __half* __restrict__ Wh1, const __half* __restrict__ Wl1,
    const float* __restrict__ b1, float* __restrict__ C1,
    const __half* __restrict__ Wh2, const __half* __restrict__ Wl2,
    const float* __restrict__ b2, float* __restrict__ C2)
{
    extern __shared__ char smem[];
    const u32 sbase = smem_u32(smem);
    float* sf = (float*)(smem + SD);
    const int tid = threadIdx.x;
    const int lane = tid & 31;
    const int wid = tid >> 5;
    const int warp_m = wid >> 1, warp_n = wid & 1;
    const int bm = blockIdx.x * 128;

    const int a_row = warp_m * 32 + ((lane >> 3) & 1) * 8 + (lane & 7);
    const int a_col = (lane >> 4) * 8;
    const u32 a_base = (u32)(a_row * PAD2 + a_col) * 2;
    const int b_row = warp_n * 64 + (lane >> 4) * 8 + (lane & 7);
    const int b_col = ((lane >> 3) & 1) * 8;
    const u32 b_base = (u32)(b_row * PAD2 + b_col) * 2;

    float acc[2][8][4];

    load_A(A, smem, bm, N_NODES, tid, true);
    load_W(Wh1, Wl1, sbase, tid);
    __syncthreads();

    zero_acc(acc);
    mma_loop(sbase, a_base, b_base, acc);
    __syncthreads();                       // all LDSM of W1 done before D overlay
    stage_D(sf, warp_m, warp_n, lane, acc);
    __syncthreads();
    store_C(sf, C1, b1, bm, N_NODES, tid);
    __syncthreads();                       // D reads done before W2 overwrites

    load_W(Wh2, Wl2, sbase, tid);
    __syncthreads();
    zero_acc(acc);
    mma_loop(sbase, a_base, b_base, acc);
    __syncthreads();
    stage_D(sf, warp_m, warp_n, lane, acc);
    __syncthreads();
    store_C(sf, C2, b2, bm, N_NODES, tid);
}

// ---------------- fused edge kernel: projection + score + scatter ------------
__global__ __launch_bounds__(256, 2) void edge_fused(
    const float* __restrict__ A,
    const __half* __restrict__ Wh, const __half* __restrict__ Wl,
    const int* __restrict__ src, const int* __restrict__ dst,
    const float* __restrict__ attn, float* __restrict__ out)
{
    extern __shared__ char smem[];
    const u32 sbase = smem_u32(smem);
    float* sf = (float*)(smem + SD);
    const int tid = threadIdx.x;
    const int lane = tid & 31;
    const int wid = tid >> 5;
    const int warp_m = wid >> 1, warp_n = wid & 1;
    const int bm = blockIdx.x * 128;

    // preload this warp's 16 (src,dst) pairs into lanes 0..15
    int s_pre = 0, d_pre = 0;
    if (lane < 16) {
        s_pre = __ldg(src + bm + wid * 16 + lane);
        d_pre = __ldg(dst + bm + wid * 16 + lane);
    }

    const int a_row = warp_m * 32 + ((lane >> 3) & 1) * 8 + (lane & 7);
    const int a_col = (lane >> 4) * 8;
    const u32 a_base = (u32)(a_row * PAD2 + a_col) * 2;
    const int b_row = warp_n * 64 + (lane >> 4) * 8 + (lane & 7);
    const int b_col = ((lane >> 3) & 1) * 8;
    const u32 b_base = (u32)(b_row * PAD2 + b_col) * 2;

    float acc[2][8][4];
    zero_acc(acc);

    load_A(A, smem, bm, N_EDGES, tid, false);
    load_W(Wh, Wl, sbase, tid);
    __syncthreads();

    mma_loop(sbase, a_base, b_base, acc);
    __syncthreads();
    stage_D(sf, warp_m, warp_n, lane, acc);
    __syncthreads();

    // ---- GATv2 edge epilogue: warp per edge, 16 edges/warp ----
    const float4 at = *(const float4*)(attn + lane * 4);
#pragma unroll 4
    for (int t = 0; t < 16; t++) {
        int el = wid * 16 + t;
        int s = __shfl_sync(0xffffffffu, s_pre, t);
        int d = __shfl_sync(0xffffffffu, d_pre, t);

        float4 fe = *(const float4*)&sf[el * 132 + lane * 4];
        float4 fs = *(const float4*)(g_feat_src + (size_t)s * FEAT + lane * 4);
        float4 fd = *(const float4*)(g_feat_dst + (size_t)d * FEAT + lane * 4);

        float t0 = fs.x + fd.x + fe.x;
        float t1 = fs.y + fd.y + fe.y;
        float t2 = fs.z + fd.z + fe.z;
        float t3 = fs.w + fd.w + fe.w;
        float l0 = (t0 >= 0.f) ? t0 : NEG_SLOPE * t0;
        float l1 = (t1 >= 0.f) ? t1 : NEG_SLOPE * t1;
        float l2 = (t2 >= 0.f) ? t2 : NEG_SLOPE * t2;
        float l3 = (t3 >= 0.f) ? t3 : NEG_SLOPE * t3;

        float p = l0 * at.x + l1 * at.y + l2 * at.z + l3 * at.w;
        p += __shfl_xor_sync(0xffffffffu, p, 1);
        p += __shfl_xor_sync(0xffffffffu, p, 2);

        float ex = __expf(p);

        if ((lane & 3) == 0)
            atomicAdd(&g_z[(size_t)d * HEADS + (lane >> 2)], ex);

        float mx = (fs.x + fe.x) * ex;
        float my = (fs.y + fe.y) * ex;
        float mz = (fs.z + fe.z) * ex;
        float mw = (fs.w + fe.w) * ex;

        float* op = out + (size_t)d * FEAT + lane * 4;
        asm volatile("red.global.add.v4.f32 [%0], {%1,%2,%3,%4};"
                     :: "l"(op), "f"(mx), "f"(my), "f"(mz), "f"(mw)
                     : "memory");
    }
}

// ---------------- K3: finalize out = relu(acc / z) ---------------------------
__global__ void finalize(float* __restrict__ out)
{
    int i = blockIdx.x * blockDim.x + threadIdx.x;
    if (i >= N_NODES * 32) return;
    int n = i >> 5;
    int q = i & 31;
    int h = q >> 2;
    float z = g_z[(size_t)n * HEADS + h];
    float inv = (z > 0.f) ? (1.f / z) : 0.f;
    float4 v = *(float4*)(out + (size_t)n * FEAT + q * 4);
    v.x = fmaxf(v.x * inv, 0.f);
    v.y = fmaxf(v.y * inv, 0.f);
    v.z = fmaxf(v.z * inv, 0.f);
    v.w = fmaxf(v.w * inv, 0.f);
    *(float4*)(out + (size_t)n * FEAT + q * 4) = v;
}

// ---------------- launch -----------------------------------------------------
extern "C" void kernel_launch(void* const* d_in, const int* in_sizes, int n_in,
                              void* d_out, int out_size)
{
    const float* x      = (const float*)d_in[0];
    const float* efeat  = (const float*)d_in[1];
    const int*   src    = (const int*)d_in[2];
    const int*   dst    = (const int*)d_in[3];
    const float* W_src  = (const float*)d_in[4];
    const float* b_src  = (const float*)d_in[5];
    const float* W_dst  = (const float*)d_in[6];
    const float* b_dst  = (const float*)d_in[7];
    const float* W_edge = (const float*)d_in[8];
    const float* attn   = (const float*)d_in[9];
    float* out = (float*)d_out;

    float *p_fsrc = nullptr, *p_fdst = nullptr;
    __half* p_w = nullptr;
    cudaGetSymbolAddress((void**)&p_fsrc, g_feat_src);
    cudaGetSymbolAddress((void**)&p_fdst, g_feat_dst);
    cudaGetSymbolAddress((void**)&p_w, g_wsplit);

    cudaFuncSetAttribute(node_dual,
                         cudaFuncAttributeMaxDynamicSharedMemorySize, SMEM_BYTES);
    cudaFuncSetAttribute(edge_fused,
                         cudaFuncAttributeMaxDynamicSharedMemorySize, SMEM_BYTES);

    // zero + weight split prep
    zero_kernel<<<(N_NODES * 32 + 255) / 256, 256>>>((float4*)out);
    prep_w<<<(3 * FEAT * FEAT + 255) / 256, 256>>>(W_src, W_dst, W_edge);

    const int WSZ = FEAT * FEAT;
    // node projections (one kernel, A tile shared)
    int nb_node = (N_NODES + 127) / 128;   // 391
    node_dual<<<nb_node, 256, SMEM_BYTES>>>(
        x, p_w + 0 * WSZ, p_w + 1 * WSZ, b_src, p_fsrc,
           p_w + 2 * WSZ, p_w + 3 * WSZ, b_dst, p_fdst);

    // fused edge projection + score + scatter
    int nb_edge = N_EDGES / 128;           // 6250
    edge_fused<<<nb_edge, 256, SMEM_BYTES>>>(
        efeat, p_w + 4 * WSZ, p_w + 5 * WSZ, src, dst, attn, out);

    // normalize + relu
    finalize<<<(N_NODES * 32 + 255) / 256, 256>>>(out);
}

// round 9
// speedup vs baseline: 2.7479x; 1.0210x over previous
#include <cuda_runtime.h>
#include <cuda_fp16.h>
#include <cstdint>
#include <cstddef>

#define N_NODES 50000
#define N_EDGES 800000
#define FEAT    128
#define HEADS   8
#define NEG_SLOPE 0.2f
#define NT      6250        // edge tiles
#define GRID_P  148         // persistent CTAs (1 per SM)

typedef unsigned long long u64;
typedef unsigned int u32;

// ---------------- device scratch ---------------------------------------------
__device__ float g_feat_src[(size_t)N_NODES * FEAT];
__device__ float g_feat_dst[(size_t)N_NODES * FEAT];
__device__ float g_z[(size_t)N_NODES * HEADS];
__device__ __half g_wsplit[3 * 2 * FEAT * FEAT];

// ---------------- smem maps ---------------------------------------------------
#define PAD2    136
#define SA      0
#define SW_H    34816
#define SW_L    69632
// node kernel: D overlays W region
#define SD_N    34816
#define SMEM_N  104448
// edge persistent kernel: D has its own region (A/W stay live across tiles)
#define SD_E    104448
#define SMEM_E  172032

// ---------------- helpers -----------------------------------------------------
__device__ __forceinline__ u32 smem_u32(const void* p) {
    u32 a;
    asm("{ .reg .u64 t; cvta.to.shared.u64 t, %1; cvt.u32.u64 %0, t; }"
        : "=r"(a) : "l"(p));
    return a;
}
__device__ __forceinline__ void ldsm4(u32& r0, u32& r1, u32& r2, u32& r3, u32 addr) {
    asm volatile("ldmatrix.sync.aligned.m8n8.x4.shared.b16 {%0,%1,%2,%3}, [%4];"
                 : "=r"(r0), "=r"(r1), "=r"(r2), "=r"(r3) : "r"(addr));
}
__device__ __forceinline__ void mma_f16(float* c, const u32* a, u32 b0, u32 b1) {
    asm volatile("mma.sync.aligned.m16n8k16.row.col.f32.f16.f16.f32 "
                 "{%0,%1,%2,%3}, {%4,%5,%6,%7}, {%8,%9}, {%0,%1,%2,%3};"
                 : "+f"(c[0]), "+f"(c[1]), "+f"(c[2]), "+f"(c[3])
                 : "r"(a[0]), "r"(a[1]), "r"(a[2]), "r"(a[3]), "r"(b0), "r"(b1));
}
__device__ __forceinline__ u64 cvt4_f16(float4 v) {
    u32 p01, p23;
    asm("cvt.rn.f16x2.f32 %0, %1, %2;" : "=r"(p01) : "f"(v.y), "f"(v.x));
    asm("cvt.rn.f16x2.f32 %0, %1, %2;" : "=r"(p23) : "f"(v.w), "f"(v.z));
    return (u64)p01 | ((u64)p23 << 32);
}
__device__ __forceinline__ void cp_async16(u32 saddr, const void* gaddr) {
    asm volatile("cp.async.cg.shared.global [%0], [%1], 16;"
                 :: "r"(saddr), "l"(gaddr) : "memory");
}
__device__ __forceinline__ void cp_async_wait_all() {
    asm volatile("cp.async.commit_group;" ::: "memory");
    asm volatile("cp.async.wait_group 0;" ::: "memory");
}

// ---------------- K0: zero ----------------------------------------------------
__global__ void zero_kernel(float4* __restrict__ out4)
{
    int i = blockIdx.x * blockDim.x + threadIdx.x;
    if (i < N_NODES * 32) out4[i] = make_float4(0.f, 0.f, 0.f, 0.f);
    if (i < N_NODES * HEADS / 4) ((float4*)g_z)[i] = make_float4(0.f, 0.f, 0.f, 0.f);
}

// ---------------- K-prep: weight fp16 hi/lo splits ----------------------------
__global__ void prep_w(const float* __restrict__ Ws, const float* __restrict__ Wd,
                       const float* __restrict__ We)
{
    int idx = blockIdx.x * blockDim.x + threadIdx.x;
    if (idx >= 3 * FEAT * FEAT) return;
    int w = idx / (FEAT * FEAT);
    int i = idx - w * (FEAT * FEAT);
    const float* srcp = (w == 0) ? Ws : (w == 1) ? Wd : We;
    float v = srcp[i];
    __half hi = __float2half_rn(v);
    __half lo = __float2half_rn(v - __half2float(hi));
    g_wsplit[(w * 2 + 0) * FEAT * FEAT + i] = hi;
    g_wsplit[(w * 2 + 1) * FEAT * FEAT + i] = lo;
}

// ================= node kernel (256 thr, 2 CTA/SM) — unchanged from R8 =======
__device__ __forceinline__ void load_A_n(const float* __restrict__ A, char* smem,
                                         int bm, int M, int tid)
{
#pragma unroll
    for (int it = 0; it < 16; it++) {
        int idx = it * 256 + tid;
        int row = idx >> 5;
        int c4  = (idx & 31) << 2;
        float4 av = make_float4(0.f, 0.f, 0.f, 0.f);
        if (bm + row < M)
            av = *(const float4*)(A + (size_t)(bm + row) * FEAT + c4);
        *(u64*)(smem + SA + (u32)(row * PAD2 + c4) * 2) = cvt4_f16(av);
    }
}
__device__ __forceinline__ void load_W_n(const __half* __restrict__ Wh,
                                         const __half* __restrict__ Wl,
                                         u32 sbase, int tid)
{
#pragma unroll
    for (int it = 0; it < 8; it++) {
        int idx = it * 256 + tid;
        int row = idx >> 4;
        int c8  = (idx & 15) << 3;
        u32 soff = (u32)(row * PAD2 + c8) * 2;
        cp_async16(sbase + SW_H + soff, Wh + (size_t)row * FEAT + c8);
        cp_async16(sbase + SW_L + soff, Wl + (size_t)row * FEAT + c8);
    }
    cp_async_wait_all();
}
__device__ __forceinline__ void mma_loop8(u32 sbase, u32 a_base, u32 b_base,
                                          float acc[2][8][4])
{
#pragma unroll
    for (int ks = 0; ks < 8; ks++) {
        const u32 koff = (u32)ks * 32;
        u32 ah[2][4];
        ldsm4(ah[0][0], ah[0][1], ah[0][2], ah[0][3], sbase + SA + a_base + koff);
        ldsm4(ah[1][0], ah[1][1], ah[1][2], ah[1][3],
              sbase + SA + a_base + (u32)(16 * PAD2) * 2 + koff);
#pragma unroll
        for (int p = 0; p < 4; p++) {
            const u32 poff = (u32)(p * 16 * PAD2) * 2 + koff;
            u32 bh[4], bl[4];
            ldsm4(bh[0], bh[1], bh[2], bh[3], sbase + SW_H + b_base + poff);
            ldsm4(bl[0], bl[1], bl[2], bl[3], sbase + SW_L + b_base + poff);
            int g0 = 2 * p, g1 = 2 * p + 1;
            mma_f16(acc[0][g0], ah[0], bh[0], bh[1]);
            mma_f16(acc[1][g0], ah[1], bh[0], bh[1]);
            mma_f16(acc[0][g1], ah[0], bh[2], bh[3]);
            mma_f16(acc[1][g1], ah[1], bh[2], bh[3]);
            mma_f16(acc[0][g0], ah[0], bl[0], bl[1]);
            mma_f16(acc[1][g0], ah[1], bl[0], bl[1]);
            mma_f16(acc[0][g1], ah[0], bl[2], bl[3]);
            mma_f16(acc[1][g1], ah[1], bl[2], bl[3]);
        }
    }
}
__device__ __forceinline__ void stage_D8(float* sf, int warp_m, int warp_n, int lane,
                                         float acc[2][8][4])
{
#pragma unroll
    for (int mi = 0; mi < 2; mi++) {
        int r0 = warp_m * 32 + mi * 16 + (lane >> 2);
        int cc = warp_n * 64 + (lane & 3) * 2;
#pragma unroll
        for (int ng = 0; ng < 8; ng++) {
            int col = cc + ng * 8;
            *(float2*)&sf[r0 * 132 + col] =
                make_float2(acc[mi][ng][0], acc[mi][ng][1]);
            *(float2*)&sf[(r0 + 8) * 132 + col] =
                make_float2(acc[mi][ng][2], acc[mi][ng][3]);
        }
    }
}
__device__ __forceinline__ void store_C(const float* sf, float* __restrict__ C,
                                        const float* __restrict__ bias,
                                        int bm, int M, int tid)
{
    float4 b4 = *(const float4*)(bias + (tid & 31) * 4);
#pragma unroll 4
    for (int i = 0; i < 16; i++) {
        int row = i * 8 + (tid >> 5);
        int gr = bm + row;
        if (gr < M) {
            float4 v = *(const float4*)&sf[row * 132 + (tid & 31) * 4];
            v.x += b4.x; v.y += b4.y; v.z += b4.z; v.w += b4.w;
            *(float4*)(C + (size_t)gr * FEAT + (tid & 31) * 4) = v;
        }
    }
}

__global__ __launch_bounds__(256, 2) void node_dual(
    const float* __restrict__ A,
    const __half* __restrict__ Wh1, const __half* __restrict__ Wl1,
    const float* __restrict__ b1, float* __restrict__ C1,
    const __half* __restrict__ Wh2, const __half* __restrict__ Wl2,
    const float* __restrict__ b2, float* __restrict__ C2)
{
    extern __shared__ char smem[];
    const u32 sbase = smem_u32(smem);
    float* sf = (float*)(smem + SD_N);
    const int tid = threadIdx.x;
    const int lane = tid & 31;
    const int wid = tid >> 5;
    const int warp_m = wid >> 1, warp_n = wid & 1;
    const int bm = blockIdx.x * 128;

    const int a_row = warp_m * 32 + ((lane >> 3) & 1) * 8 + (lane & 7);
    const int a_col = (lane >> 4) * 8;
    const u32 a_base = (u32)(a_row * PAD2 + a_col) * 2;
    const int b_row = warp_n * 64 + (lane >> 4) * 8 + (lane & 7);
    const int b_col = ((lane >> 3) & 1) * 8;
    const u32 b_base = (u32)(b_row * PAD2 + b_col) * 2;

    float acc[2][8][4];

    load_A_n(A, smem, bm, N_NODES, tid);
    load_W_n(Wh1, Wl1, sbase, tid);
    __syncthreads();

#pragma unroll
    for (int mi = 0; mi < 2; mi++)
#pragma unroll
        for (int ng = 0; ng < 8; ng++)
#pragma unroll
            for (int j = 0; j < 4; j++) acc[mi][ng][j] = 0.0f;
    mma_loop8(sbase, a_base, b_base, acc);
    __syncthreads();
    stage_D8(sf, warp_m, warp_n, lane, acc);
    __syncthreads();
    store_C(sf, C1, b1, bm, N_NODES, tid);
    __syncthreads();

    load_W_n(Wh2, Wl2, sbase, tid);
    __syncthreads();
#pragma unroll
    for (int mi = 0; mi < 2; mi++)
#pragma unroll
        for (int ng = 0; ng < 8; ng++)
#pragma unroll
            for (int j = 0; j < 4; j++) acc[mi][ng][j] = 0.0f;
    mma_loop8(sbase, a_base, b_base, acc);
    __syncthreads();
    stage_D8(sf, warp_m, warp_n, lane, acc);
    __syncthreads();
    store_C(sf, C2, b2, bm, N_NODES, tid);
}

// ================= edge kernel: persistent, 512 thr, 1 CTA/SM ================
__global__ __launch_bounds__(512, 1) void edge_persist(
    const float* __restrict__ A,
    const __half* __restrict__ Wh, const __half* __restrict__ Wl,
    const int* __restrict__ src, const int* __restrict__ dst,
    const float* __restrict__ attn, float* __restrict__ out)
{
    extern __shared__ char smem[];
    const u32 sbase = smem_u32(smem);
    float* sf = (float*)(smem + SD_E);
    const int tid = threadIdx.x;
    const int lane = tid & 31;
    const int wid = tid >> 5;                  // 0..15
    const int warp_m = wid >> 2, warp_n = wid & 3;   // 4x4 warp grid, 32x32 tiles

    // ---- W hi/lo loaded ONCE per CTA ----
#pragma unroll
    for (int it = 0; it < 4; it++) {
        int idx = it * 512 + tid;              // 0..2047 uint4 per tile
        int row = idx >> 4;
        int c8  = (idx & 15) << 3;
        u32 soff = (u32)(row * PAD2 + c8) * 2;
        cp_async16(sbase + SW_H + soff, Wh + (size_t)row * FEAT + c8);
        cp_async16(sbase + SW_L + soff, Wl + (size_t)row * FEAT + c8);
    }
    cp_async_wait_all();

    const float4 at = *(const float4*)(attn + lane * 4);

    const int a_row = warp_m * 32 + ((lane >> 3) & 1) * 8 + (lane & 7);
    const int a_col = (lane >> 4) * 8;
    const u32 a_base = (u32)(a_row * PAD2 + a_col) * 2;
    const int b_row = warp_n * 32 + (lane >> 4) * 8 + (lane & 7);
    const int b_col = ((lane >> 3) & 1) * 8;
    const u32 b_base = (u32)(b_row * PAD2 + b_col) * 2;

    // ---- prefetch first tile into registers ----
    float4 pf[8];
    int s_pre = 0, d_pre = 0;
    const int t0 = blockIdx.x;
    if (t0 < NT) {
#pragma unroll
        for (int it = 0; it < 8; it++) {
            int idx = it * 512 + tid;
            int row = idx >> 5;
            int c4  = (idx & 31) << 2;
            pf[it] = *(const float4*)(A + ((size_t)t0 * 128 + row) * FEAT + c4);
        }
        if (lane < 8) {
            s_pre = __ldg(src + t0 * 128 + wid * 8 + lane);
            d_pre = __ldg(dst + t0 * 128 + wid * 8 + lane);
        }
    }

    for (int t = t0; t < NT; t += GRID_P) {
        // ---- store A(t) fp16 into smem from prefetch regs ----
#pragma unroll
        for (int it = 0; it < 8; it++) {
            int idx = it * 512 + tid;
            int row = idx >> 5;
            int c4  = (idx & 31) << 2;
            *(u64*)(smem + SA + (u32)(row * PAD2 + c4) * 2) = cvt4_f16(pf[it]);
        }
        int s_cur = s_pre, d_cur = d_pre;
        __syncthreads();

        // ---- prefetch A(t+GRID) — hides behind MMA + epilogue ----
        const int tn = t + GRID_P;
        if (tn < NT) {
#pragma unroll
            for (int it = 0; it < 8; it++) {
                int idx = it * 512 + tid;
                int row = idx >> 5;
                int c4  = (idx & 31) << 2;
                pf[it] = *(const float4*)(A + ((size_t)tn * 128 + row) * FEAT + c4);
            }
            if (lane < 8) {
                s_pre = __ldg(src + tn * 128 + wid * 8 + lane);
                d_pre = __ldg(dst + tn * 128 + wid * 8 + lane);
            }
        }

        // ---- MMA (warp tile 32x32, 2-term W split) ----
        float acc[2][4][4];
#pragma unroll
        for (int mi = 0; mi < 2; mi++)
#pragma unroll
            for (int ng = 0; ng < 4; ng++)
#pragma unroll
                for (int j = 0; j < 4; j++) acc[mi][ng][j] = 0.0f;

#pragma unroll
        for (int ks = 0; ks < 8; ks++) {
            const u32 koff = (u32)ks * 32;
            u32 ah[2][4];
            ldsm4(ah[0][0], ah[0][1], ah[0][2], ah[0][3], sbase + SA + a_base + koff);
            ldsm4(ah[1][0], ah[1][1], ah[1][2], ah[1][3],
                  sbase + SA + a_base + (u32)(16 * PAD2) * 2 + koff);
#pragma unroll
            for (int p = 0; p < 2; p++) {
                const u32 poff = (u32)(p * 16 * PAD2) * 2 + koff;
                u32 bh[4], bl[4];
                ldsm4(bh[0], bh[1], bh[2], bh[3], sbase + SW_H + b_base + poff);
                ldsm4(bl[0], bl[1], bl[2], bl[3], sbase + SW_L + b_base + poff);
                int g0 = 2 * p, g1 = 2 * p + 1;
                mma_f16(acc[0][g0], ah[0], bh[0], bh[1]);
                mma_f16(acc[1][g0], ah[1], bh[0], bh[1]);
                mma_f16(acc[0][g1], ah[0], bh[2], bh[3]);
                mma_f16(acc[1][g1], ah[1], bh[2], bh[3]);
                mma_f16(acc[0][g0], ah[0], bl[0], bl[1]);
                mma_f16(acc[1][g0], ah[1], bl[0], bl[1]);
                mma_f16(acc[0][g1], ah[0], bl[2], bl[3]);
                mma_f16(acc[1][g1], ah[1], bl[2], bl[3]);
            }
        }

        // ---- stage D (128x132 f32) ----
#pragma unroll
        for (int mi = 0; mi < 2; mi++) {
            int r0 = warp_m * 32 + mi * 16 + (lane >> 2);
            int cc = warp_n * 32 + (lane & 3) * 2;
#pragma unroll
            for (int ng = 0; ng < 4; ng++) {
                int col = cc + ng * 8;
                *(float2*)&sf[r0 * 132 + col] =
                    make_float2(acc[mi][ng][0], acc[mi][ng][1]);
                *(float2*)&sf[(r0 + 8) * 132 + col] =
                    make_float2(acc[mi][ng][2], acc[mi][ng][3]);
            }
        }
        __syncthreads();

        // ---- GATv2 epilogue: 8 edges per warp ----
#pragma unroll
        for (int e8 = 0; e8 < 8; e8++) {
            int el = wid * 8 + e8;
            int s = __shfl_sync(0xffffffffu, s_cur, e8);
            int d = __shfl_sync(0xffffffffu, d_cur, e8);

            float4 fe = *(const float4*)&sf[el * 132 + lane * 4];
            float4 fs = *(const float4*)(g_feat_src + (size_t)s * FEAT + lane * 4);
            float4 fd = *(const float4*)(g_feat_dst + (size_t)d * FEAT + lane * 4);

            float t0v = fs.x + fd.x + fe.x;
            float t1v = fs.y + fd.y + fe.y;
            float t2v = fs.z + fd.z + fe.z;
            float t3v = fs.w + fd.w + fe.w;
            float l0 = (t0v >= 0.f) ? t0v : NEG_SLOPE * t0v;
            float l1 = (t1v >= 0.f) ? t1v : NEG_SLOPE * t1v;
            float l2 = (t2v >= 0.f) ? t2v : NEG_SLOPE * t2v;
            float l3 = (t3v >= 0.f) ? t3v : NEG_SLOPE * t3v;

            float p = l0 * at.x + l1 * at.y + l2 * at.z + l3 * at.w;
            p += __shfl_xor_sync(0xffffffffu, p, 1);
            p += __shfl_xor_sync(0xffffffffu, p, 2);

            float ex = __expf(p);

            if ((lane & 3) == 0)
                atomicAdd(&g_z[(size_t)d * HEADS + (lane >> 2)], ex);

            float mx = (fs.x + fe.x) * ex;
            float my = (fs.y + fe.y) * ex;
            float mz = (fs.z + fe.z) * ex;
            float mw = (fs.w + fe.w) * ex;

            float* op = out + (size_t)d * FEAT + lane * 4;
            asm volatile("red.global.add.v4.f32 [%0], {%1,%2,%3,%4};"
                         :: "l"(op), "f"(mx), "f"(my), "f"(mz), "f"(mw)
                         : "memory");
        }
        __syncthreads();
    }
}

// ---------------- finalize out = relu(acc / z) --------------------------------
__global__ void finalize(float* __restrict__ out)
{
    int i = blockIdx.x * blockDim.x + threadIdx.x;
    if (i >= N_NODES * 32) return;
    int n = i >> 5;
    int q = i & 31;
    int h = q >> 2;
    float z = g_z[(size_t)n * HEADS + h];
    float inv = (z > 0.f) ? (1.f / z) : 0.f;
    float4 v = *(float4*)(out + (size_t)n * FEAT + q * 4);
    v.x = fmaxf(v.x * inv, 0.f);
    v.y = fmaxf(v.y * inv, 0.f);
    v.z = fmaxf(v.z * inv, 0.f);
    v.w = fmaxf(v.w * inv, 0.f);
    *(float4*)(out + (size_t)n * FEAT + q * 4) = v;
}

// ---------------- launch -----------------------------------------------------
extern "C" void kernel_launch(void* const* d_in, const int* in_sizes, int n_in,
                              void* d_out, int out_size)
{
    const float* x      = (const float*)d_in[0];
    const float* efeat  = (const float*)d_in[1];
    const int*   src    = (const int*)d_in[2];
    const int*   dst    = (const int*)d_in[3];
    const float* W_src  = (const float*)d_in[4];
    const float* b_src  = (const float*)d_in[5];
    const float* W_dst  = (const float*)d_in[6];
    const float* b_dst  = (const float*)d_in[7];
    const float* W_edge = (const float*)d_in[8];
    const float* attn   = (const float*)d_in[9];
    float* out = (float*)d_out;

    float *p_fsrc = nullptr, *p_fdst = nullptr;
    __half* p_w = nullptr;
    cudaGetSymbolAddress((void**)&p_fsrc, g_feat_src);
    cudaGetSymbolAddress((void**)&p_fdst, g_feat_dst);
    cudaGetSymbolAddress((void**)&p_w, g_wsplit);

    cudaFuncSetAttribute(node_dual,
                         cudaFuncAttributeMaxDynamicSharedMemorySize, SMEM_N);
    cudaFuncSetAttribute(edge_persist,
                         cudaFuncAttributeMaxDynamicSharedMemorySize, SMEM_E);

    zero_kernel<<<(N_NODES * 32 + 255) / 256, 256>>>((float4*)out);
    prep_w<<<(3 * FEAT * FEAT + 255) / 256, 256>>>(W_src, W_dst, W_edge);

    const int WSZ = FEAT * FEAT;
    int nb_node = (N_NODES + 127) / 128;   // 391
    node_dual<<<nb_node, 256, SMEM_N>>>(
        x, p_w + 0 * WSZ, p_w + 1 * WSZ, b_src, p_fsrc,
           p_w + 2 * WSZ, p_w + 3 * WSZ, b_dst, p_fdst);

    edge_persist<<<GRID_P, 512, SMEM_E>>>(
        efeat, p_w + 4 * WSZ, p_w + 5 * WSZ, src, dst, attn, out);

    finalize<<<(N_NODES * 32 + 255) / 256, 256>>>(out);
}

// round 10
// speedup vs baseline: 3.2437x; 1.1804x over previous
#include <cuda_runtime.h>
#include <cuda_fp16.h>
#include <cstdint>
#include <cstddef>

#define N_NODES 50000
#define N_EDGES 800000
#define FEAT    128
#define HEADS   8
#define NEG_SLOPE 0.2f
#define NT2     12500       // 64-edge tiles
#define GRID_P2 296         // persistent CTAs (2 per SM)

typedef unsigned long long u64;
typedef unsigned int u32;

// ---------------- device scratch ---------------------------------------------
__device__ float g_feat_src[(size_t)N_NODES * FEAT];
__device__ float g_feat_dst[(size_t)N_NODES * FEAT];
__device__ float g_z[(size_t)N_NODES * HEADS];
__device__ __half g_wsplit[3 * 2 * FEAT * FEAT];

// ---------------- smem maps ---------------------------------------------------
#define PAD2    136
// node kernel (256 thr, 2 CTA/SM): full-K tiles as in R8
#define SA_N    0
#define SWH_N   34816
#define SWL_N   69632
#define SD_N    34816
#define SMEM_N  104448
// edge kernel (256 thr, 2 CTA/SM): 64-row A, fp16 W (hi only), f32 D
#define SA_E    0               // 64 x 136 fp16  = 17408
#define SW_E    17408           // 128 x 136 fp16 = 34816
#define SD_E    52224           // 64 x 132 f32   = 33792
#define SMEM_E  86016

// ---------------- helpers -----------------------------------------------------
__device__ __forceinline__ u32 smem_u32(const void* p) {
    u32 a;
    asm("{ .reg .u64 t; cvta.to.shared.u64 t, %1; cvt.u32.u64 %0, t; }"
        : "=r"(a) : "l"(p));
    return a;
}
__device__ __forceinline__ void ldsm4(u32& r0, u32& r1, u32& r2, u32& r3, u32 addr) {
    asm volatile("ldmatrix.sync.aligned.m8n8.x4.shared.b16 {%0,%1,%2,%3}, [%4];"
                 : "=r"(r0), "=r"(r1), "=r"(r2), "=r"(r3) : "r"(addr));
}
__device__ __forceinline__ void mma_f16(float* c, const u32* a, u32 b0, u32 b1) {
    asm volatile("mma.sync.aligned.m16n8k16.row.col.f32.f16.f16.f32 "
                 "{%0,%1,%2,%3}, {%4,%5,%6,%7}, {%8,%9}, {%0,%1,%2,%3};"
                 : "+f"(c[0]), "+f"(c[1]), "+f"(c[2]), "+f"(c[3])
                 : "r"(a[0]), "r"(a[1]), "r"(a[2]), "r"(a[3]), "r"(b0), "r"(b1));
}
__device__ __forceinline__ u64 cvt4_f16(float4 v) {
    u32 p01, p23;
    asm("cvt.rn.f16x2.f32 %0, %1, %2;" : "=r"(p01) : "f"(v.y), "f"(v.x));
    asm("cvt.rn.f16x2.f32 %0, %1, %2;" : "=r"(p23) : "f"(v.w), "f"(v.z));
    return (u64)p01 | ((u64)p23 << 32);
}
__device__ __forceinline__ void cp_async16(u32 saddr, const void* gaddr) {
    asm volatile("cp.async.cg.shared.global [%0], [%1], 16;"
                 :: "r"(saddr), "l"(gaddr) : "memory");
}
__device__ __forceinline__ void cp_async_wait_all() {
    asm volatile("cp.async.commit_group;" ::: "memory");
    asm volatile("cp.async.wait_group 0;" ::: "memory");
}

// ---------------- K0: zero ----------------------------------------------------
__global__ void zero_kernel(float4* __restrict__ out4)
{
    int i = blockIdx.x * blockDim.x + threadIdx.x;
    if (i < N_NODES * 32) out4[i] = make_float4(0.f, 0.f, 0.f, 0.f);
    if (i < N_NODES * HEADS / 4) ((float4*)g_z)[i] = make_float4(0.f, 0.f, 0.f, 0.f);
}

// ---------------- K-prep: weight fp16 hi/lo splits ----------------------------
__global__ void prep_w(const float* __restrict__ Ws, const float* __restrict__ Wd,
                       const float* __restrict__ We)
{
    int idx = blockIdx.x * blockDim.x + threadIdx.x;
    if (idx >= 3 * FEAT * FEAT) return;
    int w = idx / (FEAT * FEAT);
    int i = idx - w * (FEAT * FEAT);
    const float* srcp = (w == 0) ? Ws : (w == 1) ? Wd : We;
    float v = srcp[i];
    __half hi = __float2half_rn(v);
    __half lo = __float2half_rn(v - __half2float(hi));
    g_wsplit[(w * 2 + 0) * FEAT * FEAT + i] = hi;
    g_wsplit[(w * 2 + 1) * FEAT * FEAT + i] = lo;
}

// ================= node kernel (unchanged, 2-term W split) ===================
__global__ __launch_bounds__(256, 2) void node_dual(
    const float* __restrict__ A,
    const __half* __restrict__ Wh1, const __half* __restrict__ Wl1,
    const float* __restrict__ b1, float* __restrict__ C1,
    const __half* __restrict__ Wh2, const __half* __restrict__ Wl2,
    const float* __restrict__ b2, float* __restrict__ C2)
{
    extern __shared__ char smem[];
    const u32 sbase = smem_u32(smem);
    float* sf = (float*)(smem + SD_N);
    const int tid = threadIdx.x;
    const int lane = tid & 31;
    const int wid = tid >> 5;
    const int warp_m = wid >> 1, warp_n = wid & 1;
    const int bm = blockIdx.x * 128;

    const int a_row = warp_m * 32 + ((lane >> 3) & 1) * 8 + (lane & 7);
    const int a_col = (lane >> 4) * 8;
    const u32 a_base = (u32)(a_row * PAD2 + a_col) * 2;
    const int b_row = warp_n * 64 + (lane >> 4) * 8 + (lane & 7);
    const int b_col = ((lane >> 3) & 1) * 8;
    const u32 b_base = (u32)(b_row * PAD2 + b_col) * 2;

    float acc[2][8][4];

    // load A (f32 -> fp16), cp.async W1 hi/lo
#pragma unroll
    for (int it = 0; it < 16; it++) {
        int idx = it * 256 + tid;
        int row = idx >> 5;
        int c4  = (idx & 31) << 2;
        float4 av = make_float4(0.f, 0.f, 0.f, 0.f);
        if (bm + row < N_NODES)
            av = *(const float4*)(A + (size_t)(bm + row) * FEAT + c4);
        *(u64*)(smem + SA_N + (u32)(row * PAD2 + c4) * 2) = cvt4_f16(av);
    }
    for (int pass = 0; pass < 2; pass++) {
        const __half* Wh = pass ? Wh2 : Wh1;
        const __half* Wl = pass ? Wl2 : Wl1;
#pragma unroll
        for (int it = 0; it < 8; it++) {
            int idx = it * 256 + tid;
            int row = idx >> 4;
            int c8  = (idx & 15) << 3;
            u32 soff = (u32)(row * PAD2 + c8) * 2;
            cp_async16(sbase + SWH_N + soff, Wh + (size_t)row * FEAT + c8);
            cp_async16(sbase + SWL_N + soff, Wl + (size_t)row * FEAT + c8);
        }
        cp_async_wait_all();
        __syncthreads();

#pragma unroll
        for (int mi = 0; mi < 2; mi++)
#pragma unroll
            for (int ng = 0; ng < 8; ng++)
#pragma unroll
                for (int j = 0; j < 4; j++) acc[mi][ng][j] = 0.0f;

#pragma unroll
        for (int ks = 0; ks < 8; ks++) {
            const u32 koff = (u32)ks * 32;
            u32 ah[2][4];
            ldsm4(ah[0][0], ah[0][1], ah[0][2], ah[0][3], sbase + SA_N + a_base + koff);
            ldsm4(ah[1][0], ah[1][1], ah[1][2], ah[1][3],
                  sbase + SA_N + a_base + (u32)(16 * PAD2) * 2 + koff);
#pragma unroll
            for (int p = 0; p < 4; p++) {
                const u32 poff = (u32)(p * 16 * PAD2) * 2 + koff;
                u32 bh[4], bl[4];
                ldsm4(bh[0], bh[1], bh[2], bh[3], sbase + SWH_N + b_base + poff);
                ldsm4(bl[0], bl[1], bl[2], bl[3], sbase + SWL_N + b_base + poff);
                int g0 = 2 * p, g1 = 2 * p + 1;
                mma_f16(acc[0][g0], ah[0], bh[0], bh[1]);
                mma_f16(acc[1][g0], ah[1], bh[0], bh[1]);
                mma_f16(acc[0][g1], ah[0], bh[2], bh[3]);
                mma_f16(acc[1][g1], ah[1], bh[2], bh[3]);
                mma_f16(acc[0][g0], ah[0], bl[0], bl[1]);
                mma_f16(acc[1][g0], ah[1], bl[0], bl[1]);
                mma_f16(acc[0][g1], ah[0], bl[2], bl[3]);
                mma_f16(acc[1][g1], ah[1], bl[2], bl[3]);
            }
        }
        __syncthreads();
        // stage D over W region, then store
#pragma unroll
        for (int mi = 0; mi < 2; mi++) {
            int r0 = warp_m * 32 + mi * 16 + (lane >> 2);
            int cc = warp_n * 64 + (lane & 3) * 2;
#pragma unroll
            for (int ng = 0; ng < 8; ng++) {
                int col = cc + ng * 8;
                *(float2*)&sf[r0 * 132 + col] =
                    make_float2(acc[mi][ng][0], acc[mi][ng][1]);
                *(float2*)&sf[(r0 + 8) * 132 + col] =
                    make_float2(acc[mi][ng][2], acc[mi][ng][3]);
            }
        }
        __syncthreads();
        {
            const float* bias = pass ? b2 : b1;
            float* C = pass ? C2 : C1;
            float4 b4 = *(const float4*)(bias + (tid & 31) * 4);
#pragma unroll 4
            for (int i = 0; i < 16; i++) {
                int row = i * 8 + (tid >> 5);
                int gr = bm + row;
                if (gr < N_NODES) {
                    float4 v = *(const float4*)&sf[row * 132 + (tid & 31) * 4];
                    v.x += b4.x; v.y += b4.y; v.z += b4.z; v.w += b4.w;
                    *(float4*)(C + (size_t)gr * FEAT + (tid & 31) * 4) = v;
                }
            }
        }
        __syncthreads();
    }
}

// ======== edge kernel: persistent, 64-edge tiles, 256 thr, 2 CTA/SM ==========
__global__ __launch_bounds__(256, 2) void edge_persist(
    const float* __restrict__ A,
    const __half* __restrict__ Wh,
    const int* __restrict__ src, const int* __restrict__ dst,
    const float* __restrict__ attn, float* __restrict__ out)
{
    extern __shared__ char smem[];
    const u32 sbase = smem_u32(smem);
    float* sf = (float*)(smem + SD_E);
    const int tid = threadIdx.x;
    const int lane = tid & 31;
    const int wid = tid >> 5;                      // 0..7
    const int warp_m = wid >> 2, warp_n = wid & 3; // 2x4 grid, 32x32 warp tiles

    // ---- W (fp16, hi only) loaded ONCE per CTA ----
#pragma unroll
    for (int it = 0; it < 8; it++) {
        int idx = it * 256 + tid;                  // 0..2047 uint4
        int row = idx >> 4;
        int c8  = (idx & 15) << 3;
        cp_async16(sbase + SW_E + (u32)(row * PAD2 + c8) * 2,
                   Wh + (size_t)row * FEAT + c8);
    }
    cp_async_wait_all();

    const float4 at = *(const float4*)(attn + lane * 4);

    const int a_row = warp_m * 32 + ((lane >> 3) & 1) * 8 + (lane & 7);
    const int a_col = (lane >> 4) * 8;
    const u32 a_base = (u32)(a_row * PAD2 + a_col) * 2;
    const int b_row = warp_n * 32 + (lane >> 4) * 8 + (lane & 7);
    const int b_col = ((lane >> 3) & 1) * 8;
    const u32 b_base = (u32)(b_row * PAD2 + b_col) * 2;

    // ---- prefetch first tile (64 rows x 128 f32) + indices ----
    float4 pf[8];
    int s_pre = 0, d_pre = 0;
    const int t0 = blockIdx.x;
    if (t0 < NT2) {
#pragma unroll
        for (int it = 0; it < 8; it++) {
            int idx = it * 256 + tid;              // 0..2047 float4
            int row = idx >> 5;                    // 0..63
            int c4  = (idx & 31) << 2;
            pf[it] = *(const float4*)(A + ((size_t)t0 * 64 + row) * FEAT + c4);
        }
        if (lane < 8) {
            s_pre = __ldg(src + t0 * 64 + wid * 8 + lane);
            d_pre = __ldg(dst + t0 * 64 + wid * 8 + lane);
        }
    }

    for (int t = t0; t < NT2; t += GRID_P2) {
        // ---- store A(t) fp16 into smem from prefetch regs ----
#pragma unroll
        for (int it = 0; it < 8; it++) {
            int idx = it * 256 + tid;
            int row = idx >> 5;
            int c4  = (idx & 31) << 2;
            *(u64*)(smem + SA_E + (u32)(row * PAD2 + c4) * 2) = cvt4_f16(pf[it]);
        }
        int s_cur = s_pre, d_cur = d_pre;
        __syncthreads();

        // ---- prefetch A(t+GRID) ----
        const int tn = t + GRID_P2;
        if (tn < NT2) {
#pragma unroll
            for (int it = 0; it < 8; it++) {
                int idx = it * 256 + tid;
                int row = idx >> 5;
                int c4  = (idx & 31) << 2;
                pf[it] = *(const float4*)(A + ((size_t)tn * 64 + row) * FEAT + c4);
            }
            if (lane < 8) {
                s_pre = __ldg(src + tn * 64 + wid * 8 + lane);
                d_pre = __ldg(dst + tn * 64 + wid * 8 + lane);
            }
        }

        // ---- MMA: warp tile 32x32, fp16 W (single term) ----
        float acc[2][4][4];
#pragma unroll
        for (int mi = 0; mi < 2; mi++)
#pragma unroll
            for (int ng = 0; ng < 4; ng++)
#pragma unroll
                for (int j = 0; j < 4; j++) acc[mi][ng][j] = 0.0f;

#pragma unroll
        for (int ks = 0; ks < 8; ks++) {
            const u32 koff = (u32)ks * 32;
            u32 ah[2][4];
            ldsm4(ah[0][0], ah[0][1], ah[0][2], ah[0][3], sbase + SA_E + a_base + koff);
            ldsm4(ah[1][0], ah[1][1], ah[1][2], ah[1][3],
                  sbase + SA_E + a_base + (u32)(16 * PAD2) * 2 + koff);
#pragma unroll
            for (int p = 0; p < 2; p++) {
                const u32 poff = (u32)(p * 16 * PAD2) * 2 + koff;
                u32 bh[4];
                ldsm4(bh[0], bh[1], bh[2], bh[3], sbase + SW_E + b_base + poff);
                int g0 = 2 * p, g1 = 2 * p + 1;
                mma_f16(acc[0][g0], ah[0], bh[0], bh[1]);
                mma_f16(acc[1][g0], ah[1], bh[0], bh[1]);
                mma_f16(acc[0][g1], ah[0], bh[2], bh[3]);
                mma_f16(acc[1][g1], ah[1], bh[2], bh[3]);
            }
        }

        // ---- stage D (64 x 132 f32) ----
#pragma unroll
        for (int mi = 0; mi < 2; mi++) {
            int r0 = warp_m * 32 + mi * 16 + (lane >> 2);
            int cc = warp_n * 32 + (lane & 3) * 2;
#pragma unroll
            for (int ng = 0; ng < 4; ng++) {
                int col = cc + ng * 8;
                *(float2*)&sf[r0 * 132 + col] =
                    make_float2(acc[mi][ng][0], acc[mi][ng][1]);
                *(float2*)&sf[(r0 + 8) * 132 + col] =
                    make_float2(acc[mi][ng][2], acc[mi][ng][3]);
            }
        }
        __syncthreads();

        // ---- GATv2 epilogue: 8 edges per warp ----
#pragma unroll
        for (int e8 = 0; e8 < 8; e8++) {
            int el = wid * 8 + e8;
            int s = __shfl_sync(0xffffffffu, s_cur, e8);
            int d = __shfl_sync(0xffffffffu, d_cur, e8);

            float4 fe = *(const float4*)&sf[el * 132 + lane * 4];
            float4 fs = *(const float4*)(g_feat_src + (size_t)s * FEAT + lane * 4);
            float4 fd = *(const float4*)(g_feat_dst + (size_t)d * FEAT + lane * 4);

            float t0v = fs.x + fd.x + fe.x;
            float t1v = fs.y + fd.y + fe.y;
            float t2v = fs.z + fd.z + fe.z;
            float t3v = fs.w + fd.w + fe.w;
            float l0 = (t0v >= 0.f) ? t0v : NEG_SLOPE * t0v;
            float l1 = (t1v >= 0.f) ? t1v : NEG_SLOPE * t1v;
            float l2 = (t2v >= 0.f) ? t2v : NEG_SLOPE * t2v;
            float l3 = (t3v >= 0.f) ? t3v : NEG_SLOPE * t3v;

            float p = l0 * at.x + l1 * at.y + l2 * at.z + l3 * at.w;
            p += __shfl_xor_sync(0xffffffffu, p, 1);
            p += __shfl_xor_sync(0xffffffffu, p, 2);

            float ex = __expf(p);

            if ((lane & 3) == 0)
                atomicAdd(&g_z[(size_t)d * HEADS + (lane >> 2)], ex);

            float mx = (fs.x + fe.x) * ex;
            float my = (fs.y + fe.y) * ex;
            float mz = (fs.z + fe.z) * ex;
            float mw = (fs.w + fe.w) * ex;

            float* op = out + (size_t)d * FEAT + lane * 4;
            asm volatile("red.global.add.v4.f32 [%0], {%1,%2,%3,%4};"
                         :: "l"(op), "f"(mx), "f"(my), "f"(mz), "f"(mw)
                         : "memory");
        }
        __syncthreads();
    }
}

// ---------------- finalize out = relu(acc / z) --------------------------------
__global__ void finalize(float* __restrict__ out)
{
    int i = blockIdx.x * blockDim.x + threadIdx.x;
    if (i >= N_NODES * 32) return;
    int n = i >> 5;
    int q = i & 31;
    int h = q >> 2;
    float z = g_z[(size_t)n * HEADS + h];
    float inv = (z > 0.f) ? (1.f / z) : 0.f;
    float4 v = *(float4*)(out + (size_t)n * FEAT + q * 4);
    v.x = fmaxf(v.x * inv, 0.f);
    v.y = fmaxf(v.y * inv, 0.f);
    v.z = fmaxf(v.z * inv, 0.f);
    v.w = fmaxf(v.w * inv, 0.f);
    *(float4*)(out + (size_t)n * FEAT + q * 4) = v;
}

// ---------------- launch -----------------------------------------------------
extern "C" void kernel_launch(void* const* d_in, const int* in_sizes, int n_in,
                              void* d_out, int out_size)
{
    const float* x      = (const float*)d_in[0];
    const float* efeat  = (const float*)d_in[1];
    const int*   src    = (const int*)d_in[2];
    const int*   dst    = (const int*)d_in[3];
    const float* W_src  = (const float*)d_in[4];
    const float* b_src  = (const float*)d_in[5];
    const float* W_dst  = (const float*)d_in[6];
    const float* b_dst  = (const float*)d_in[7];
    const float* W_edge = (const float*)d_in[8];
    const float* attn   = (const float*)d_in[9];
    float* out = (float*)d_out;

    float *p_fsrc = nullptr, *p_fdst = nullptr;
    __half* p_w = nullptr;
    cudaGetSymbolAddress((void**)&p_fsrc, g_feat_src);
    cudaGetSymbolAddress((void**)&p_fdst, g_feat_dst);
    cudaGetSymbolAddress((void**)&p_w, g_wsplit);

    cudaFuncSetAttribute(node_dual,
                         cudaFuncAttributeMaxDynamicSharedMemorySize, SMEM_N);
    cudaFuncSetAttribute(edge_persist,
                         cudaFuncAttributeMaxDynamicSharedMemorySize, SMEM_E);

    zero_kernel<<<(N_NODES * 32 + 255) / 256, 256>>>((float4*)out);
    prep_w<<<(3 * FEAT * FEAT + 255) / 256, 256>>>(W_src, W_dst, W_edge);

    const int WSZ = FEAT * FEAT;
    int nb_node = (N_NODES + 127) / 128;   // 391
    node_dual<<<nb_node, 256, SMEM_N>>>(
        x, p_w + 0 * WSZ, p_w + 1 * WSZ, b_src, p_fsrc,
           p_w + 2 * WSZ, p_w + 3 * WSZ, b_dst, p_fdst);

    edge_persist<<<GRID_P2, 256, SMEM_E>>>(
        efeat, p_w + 4 * WSZ, src, dst, attn, out);

    finalize<<<(N_NODES * 32 + 255) / 256, 256>>>(out);
}

// round 11
// speedup vs baseline: 3.5783x; 1.1032x over previous
#include <cuda_runtime.h>
#include <cuda_fp16.h>
#include <cstdint>
#include <cstddef>

#define N_NODES 50000
#define N_EDGES 800000
#define FEAT    128
#define HEADS   8
#define NEG_SLOPE 0.2f
#define NT2     12500       // 64-edge tiles
#define GRID_P2 296         // persistent CTAs (2 per SM)

typedef unsigned long long u64;
typedef unsigned int u32;

// ---------------- device scratch ---------------------------------------------
__device__ __half g_feat_src[(size_t)N_NODES * FEAT];   // 12.8 MB (fp16)
__device__ __half g_feat_dst[(size_t)N_NODES * FEAT];   // 12.8 MB (fp16)
__device__ float g_z[(size_t)N_NODES * HEADS];
__device__ __half g_wsplit[3 * 2 * FEAT * FEAT];

// ---------------- smem maps ---------------------------------------------------
#define PAD2    136
// node kernel (256 thr, 2 CTA/SM): full-K tiles
#define SA_N    0
#define SWH_N   34816
#define SWL_N   69632
#define SD_N    34816
#define SMEM_N  104448
// edge kernel (256 thr, 2 CTA/SM): 64-row A, fp16 W (hi only), f32 D
#define SA_E    0               // 64 x 136 fp16  = 17408
#define SW_E    17408           // 128 x 136 fp16 = 34816
#define SD_E    52224           // 64 x 132 f32   = 33792
#define SMEM_E  86016

// ---------------- helpers -----------------------------------------------------
__device__ __forceinline__ u32 smem_u32(const void* p) {
    u32 a;
    asm("{ .reg .u64 t; cvta.to.shared.u64 t, %1; cvt.u32.u64 %0, t; }"
        : "=r"(a) : "l"(p));
    return a;
}
__device__ __forceinline__ void ldsm4(u32& r0, u32& r1, u32& r2, u32& r3, u32 addr) {
    asm volatile("ldmatrix.sync.aligned.m8n8.x4.shared.b16 {%0,%1,%2,%3}, [%4];"
                 : "=r"(r0), "=r"(r1), "=r"(r2), "=r"(r3) : "r"(addr));
}
__device__ __forceinline__ void mma_f16(float* c, const u32* a, u32 b0, u32 b1) {
    asm volatile("mma.sync.aligned.m16n8k16.row.col.f32.f16.f16.f32 "
                 "{%0,%1,%2,%3}, {%4,%5,%6,%7}, {%8,%9}, {%0,%1,%2,%3};"
                 : "+f"(c[0]), "+f"(c[1]), "+f"(c[2]), "+f"(c[3])
                 : "r"(a[0]), "r"(a[1]), "r"(a[2]), "r"(a[3]), "r"(b0), "r"(b1));
}
__device__ __forceinline__ u64 cvt4_f16(float4 v) {
    u32 p01, p23;
    asm("cvt.rn.f16x2.f32 %0, %1, %2;" : "=r"(p01) : "f"(v.y), "f"(v.x));
    asm("cvt.rn.f16x2.f32 %0, %1, %2;" : "=r"(p23) : "f"(v.w), "f"(v.z));
    return (u64)p01 | ((u64)p23 << 32);
}
__device__ __forceinline__ void cp_async16(u32 saddr, const void* gaddr) {
    asm volatile("cp.async.cg.shared.global [%0], [%1], 16;"
                 :: "r"(saddr), "l"(gaddr) : "memory");
}
__device__ __forceinline__ void cp_async_wait_all() {
    asm volatile("cp.async.commit_group;" ::: "memory");
    asm volatile("cp.async.wait_group 0;" ::: "memory");
}
// gather 4 fp16 feats at [node*FEAT + lane*4] -> float4
__device__ __forceinline__ float4 gather_h4(const __half* base, int node, int lane) {
    uint2 hv = *(const uint2*)(base + (size_t)node * FEAT + lane * 4);
    __half2 h01 = *reinterpret_cast<__half2*>(&hv.x);
    __half2 h23 = *reinterpret_cast<__half2*>(&hv.y);
    float2 f01 = __half22float2(h01);
    float2 f23 = __half22float2(h23);
    return make_float4(f01.x, f01.y, f23.x, f23.y);
}

// ---------------- K0: zero ----------------------------------------------------
__global__ void zero_kernel(float4* __restrict__ out4)
{
    int i = blockIdx.x * blockDim.x + threadIdx.x;
    if (i < N_NODES * 32) out4[i] = make_float4(0.f, 0.f, 0.f, 0.f);
    if (i < N_NODES * HEADS / 4) ((float4*)g_z)[i] = make_float4(0.f, 0.f, 0.f, 0.f);
}

// ---------------- K-prep: weight fp16 hi/lo splits ----------------------------
__global__ void prep_w(const float* __restrict__ Ws, const float* __restrict__ Wd,
                       const float* __restrict__ We)
{
    int idx = blockIdx.x * blockDim.x + threadIdx.x;
    if (idx >= 3 * FEAT * FEAT) return;
    int w = idx / (FEAT * FEAT);
    int i = idx - w * (FEAT * FEAT);
    const float* srcp = (w == 0) ? Ws : (w == 1) ? Wd : We;
    float v = srcp[i];
    __half hi = __float2half_rn(v);
    __half lo = __float2half_rn(v - __half2float(hi));
    g_wsplit[(w * 2 + 0) * FEAT * FEAT + i] = hi;
    g_wsplit[(w * 2 + 1) * FEAT * FEAT + i] = lo;
}

// ================= node kernel: both projections, fp16 feat output ===========
__global__ __launch_bounds__(256, 2) void node_dual(
    const float* __restrict__ A,
    const __half* __restrict__ Wh1, const __half* __restrict__ Wl1,
    const float* __restrict__ b1, __half* __restrict__ C1,
    const __half* __restrict__ Wh2, const __half* __restrict__ Wl2,
    const float* __restrict__ b2, __half* __restrict__ C2)
{
    extern __shared__ char smem[];
    const u32 sbase = smem_u32(smem);
    float* sf = (float*)(smem + SD_N);
    const int tid = threadIdx.x;
    const int lane = tid & 31;
    const int wid = tid >> 5;
    const int warp_m = wid >> 1, warp_n = wid & 1;
    const int bm = blockIdx.x * 128;

    const int a_row = warp_m * 32 + ((lane >> 3) & 1) * 8 + (lane & 7);
    const int a_col = (lane >> 4) * 8;
    const u32 a_base = (u32)(a_row * PAD2 + a_col) * 2;
    const int b_row = warp_n * 64 + (lane >> 4) * 8 + (lane & 7);
    const int b_col = ((lane >> 3) & 1) * 8;
    const u32 b_base = (u32)(b_row * PAD2 + b_col) * 2;

    float acc[2][8][4];

    // load A (f32 -> fp16)
#pragma unroll
    for (int it = 0; it < 16; it++) {
        int idx = it * 256 + tid;
        int row = idx >> 5;
        int c4  = (idx & 31) << 2;
        float4 av = make_float4(0.f, 0.f, 0.f, 0.f);
        if (bm + row < N_NODES)
            av = *(const float4*)(A + (size_t)(bm + row) * FEAT + c4);
        *(u64*)(smem + SA_N + (u32)(row * PAD2 + c4) * 2) = cvt4_f16(av);
    }
    for (int pass = 0; pass < 2; pass++) {
        const __half* Wh = pass ? Wh2 : Wh1;
        const __half* Wl = pass ? Wl2 : Wl1;
#pragma unroll
        for (int it = 0; it < 8; it++) {
            int idx = it * 256 + tid;
            int row = idx >> 4;
            int c8  = (idx & 15) << 3;
            u32 soff = (u32)(row * PAD2 + c8) * 2;
            cp_async16(sbase + SWH_N + soff, Wh + (size_t)row * FEAT + c8);
            cp_async16(sbase + SWL_N + soff, Wl + (size_t)row * FEAT + c8);
        }
        cp_async_wait_all();
        __syncthreads();

#pragma unroll
        for (int mi = 0; mi < 2; mi++)
#pragma unroll
            for (int ng = 0; ng < 8; ng++)
#pragma unroll
                for (int j = 0; j < 4; j++) acc[mi][ng][j] = 0.0f;

#pragma unroll
        for (int ks = 0; ks < 8; ks++) {
            const u32 koff = (u32)ks * 32;
            u32 ah[2][4];
            ldsm4(ah[0][0], ah[0][1], ah[0][2], ah[0][3], sbase + SA_N + a_base + koff);
            ldsm4(ah[1][0], ah[1][1], ah[1][2], ah[1][3],
                  sbase + SA_N + a_base + (u32)(16 * PAD2) * 2 + koff);
#pragma unroll
            for (int p = 0; p < 4; p++) {
                const u32 poff = (u32)(p * 16 * PAD2) * 2 + koff;
                u32 bh[4], bl[4];
                ldsm4(bh[0], bh[1], bh[2], bh[3], sbase + SWH_N + b_base + poff);
                ldsm4(bl[0], bl[1], bl[2], bl[3], sbase + SWL_N + b_base + poff);
                int g0 = 2 * p, g1 = 2 * p + 1;
                mma_f16(acc[0][g0], ah[0], bh[0], bh[1]);
                mma_f16(acc[1][g0], ah[1], bh[0], bh[1]);
                mma_f16(acc[0][g1], ah[0], bh[2], bh[3]);
                mma_f16(acc[1][g1], ah[1], bh[2], bh[3]);
                mma_f16(acc[0][g0], ah[0], bl[0], bl[1]);
                mma_f16(acc[1][g0], ah[1], bl[0], bl[1]);
                mma_f16(acc[0][g1], ah[0], bl[2], bl[3]);
                mma_f16(acc[1][g1], ah[1], bl[2], bl[3]);
            }
        }
        __syncthreads();
        // stage D over W region
#pragma unroll
        for (int mi = 0; mi < 2; mi++) {
            int r0 = warp_m * 32 + mi * 16 + (lane >> 2);
            int cc = warp_n * 64 + (lane & 3) * 2;
#pragma unroll
            for (int ng = 0; ng < 8; ng++) {
                int col = cc + ng * 8;
                *(float2*)&sf[r0 * 132 + col] =
                    make_float2(acc[mi][ng][0], acc[mi][ng][1]);
                *(float2*)&sf[(r0 + 8) * 132 + col] =
                    make_float2(acc[mi][ng][2], acc[mi][ng][3]);
            }
        }
        __syncthreads();
        // store as fp16 (+bias)
        {
            const float* bias = pass ? b2 : b1;
            __half* C = pass ? C2 : C1;
            float4 b4 = *(const float4*)(bias + (tid & 31) * 4);
#pragma unroll 4
            for (int i = 0; i < 16; i++) {
                int row = i * 8 + (tid >> 5);
                int gr = bm + row;
                if (gr < N_NODES) {
                    float4 v = *(const float4*)&sf[row * 132 + (tid & 31) * 4];
                    v.x += b4.x; v.y += b4.y; v.z += b4.z; v.w += b4.w;
                    u64 hv = cvt4_f16(v);
                    *(u64*)(C + (size_t)gr * FEAT + (tid & 31) * 4) = hv;
                }
            }
        }
        __syncthreads();
    }
}

// ======== edge kernel: persistent, 64-edge tiles, 256 thr, 2 CTA/SM ==========
__global__ __launch_bounds__(256, 2) void edge_persist(
    const float* __restrict__ A,
    const __half* __restrict__ Wh,
    const int* __restrict__ src, const int* __restrict__ dst,
    const float* __restrict__ attn, float* __restrict__ out)
{
    extern __shared__ char smem[];
    const u32 sbase = smem_u32(smem);
    float* sf = (float*)(smem + SD_E);
    const int tid = threadIdx.x;
    const int lane = tid & 31;
    const int wid = tid >> 5;                      // 0..7
    const int warp_m = wid >> 2, warp_n = wid & 3; // 2x4 grid, 32x32 warp tiles

    // ---- W (fp16, hi only) loaded ONCE per CTA ----
#pragma unroll
    for (int it = 0; it < 8; it++) {
        int idx = it * 256 + tid;                  // 0..2047 uint4
        int row = idx >> 4;
        int c8  = (idx & 15) << 3;
        cp_async16(sbase + SW_E + (u32)(row * PAD2 + c8) * 2,
                   Wh + (size_t)row * FEAT + c8);
    }
    cp_async_wait_all();

    const float4 at = *(const float4*)(attn + lane * 4);

    const int a_row = warp_m * 32 + ((lane >> 3) & 1) * 8 + (lane & 7);
    const int a_col = (lane >> 4) * 8;
    const u32 a_base = (u32)(a_row * PAD2 + a_col) * 2;
    const int b_row = warp_n * 32 + (lane >> 4) * 8 + (lane & 7);
    const int b_col = ((lane >> 3) & 1) * 8;
    const u32 b_base = (u32)(b_row * PAD2 + b_col) * 2;

    // ---- prefetch first tile (64 rows x 128 f32) + indices ----
    float4 pf[8];
    int s_pre = 0, d_pre = 0;
    const int t0 = blockIdx.x;
    if (t0 < NT2) {
#pragma unroll
        for (int it = 0; it < 8; it++) {
            int idx = it * 256 + tid;              // 0..2047 float4
            int row = idx >> 5;                    // 0..63
            int c4  = (idx & 31) << 2;
            pf[it] = *(const float4*)(A + ((size_t)t0 * 64 + row) * FEAT + c4);
        }
        if (lane < 8) {
            s_pre = __ldg(src + t0 * 64 + wid * 8 + lane);
            d_pre = __ldg(dst + t0 * 64 + wid * 8 + lane);
        }
    }

    for (int t = t0; t < NT2; t += GRID_P2) {
        // ---- store A(t) fp16 into smem from prefetch regs ----
#pragma unroll
        for (int it = 0; it < 8; it++) {
            int idx = it * 256 + tid;
            int row = idx >> 5;
            int c4  = (idx & 31) << 2;
            *(u64*)(smem + SA_E + (u32)(row * PAD2 + c4) * 2) = cvt4_f16(pf[it]);
        }
        int s_cur = s_pre, d_cur = d_pre;
        __syncthreads();

        // ---- prefetch A(t+GRID) ----
        const int tn = t + GRID_P2;
        if (tn < NT2) {
#pragma unroll
            for (int it = 0; it < 8; it++) {
                int idx = it * 256 + tid;
                int row = idx >> 5;
                int c4  = (idx & 31) << 2;
                pf[it] = *(const float4*)(A + ((size_t)tn * 64 + row) * FEAT + c4);
            }
            if (lane < 8) {
                s_pre = __ldg(src + tn * 64 + wid * 8 + lane);
                d_pre = __ldg(dst + tn * 64 + wid * 8 + lane);
            }
        }

        // ---- MMA: warp tile 32x32, fp16 W (single term) ----
        float acc[2][4][4];
#pragma unroll
        for (int mi = 0; mi < 2; mi++)
#pragma unroll
            for (int ng = 0; ng < 4; ng++)
#pragma unroll
                for (int j = 0; j < 4; j++) acc[mi][ng][j] = 0.0f;

#pragma unroll
        for (int ks = 0; ks < 8; ks++) {
            const u32 koff = (u32)ks * 32;
            u32 ah[2][4];
            ldsm4(ah[0][0], ah[0][1], ah[0][2], ah[0][3], sbase + SA_E + a_base + koff);
            ldsm4(ah[1][0], ah[1][1], ah[1][2], ah[1][3],
                  sbase + SA_E + a_base + (u32)(16 * PAD2) * 2 + koff);
#pragma unroll
            for (int p = 0; p < 2; p++) {
                const u32 poff = (u32)(p * 16 * PAD2) * 2 + koff;
                u32 bh[4];
                ldsm4(bh[0], bh[1], bh[2], bh[3], sbase + SW_E + b_base + poff);
                int g0 = 2 * p, g1 = 2 * p + 1;
                mma_f16(acc[0][g0], ah[0], bh[0], bh[1]);
                mma_f16(acc[1][g0], ah[1], bh[0], bh[1]);
                mma_f16(acc[0][g1], ah[0], bh[2], bh[3]);
                mma_f16(acc[1][g1], ah[1], bh[2], bh[3]);
            }
        }

        // ---- stage D (64 x 132 f32) ----
#pragma unroll
        for (int mi = 0; mi < 2; mi++) {
            int r0 = warp_m * 32 + mi * 16 + (lane >> 2);
            int cc = warp_n * 32 + (lane & 3) * 2;
#pragma unroll
            for (int ng = 0; ng < 4; ng++) {
                int col = cc + ng * 8;
                *(float2*)&sf[r0 * 132 + col] =
                    make_float2(acc[mi][ng][0], acc[mi][ng][1]);
                *(float2*)&sf[(r0 + 8) * 132 + col] =
                    make_float2(acc[mi][ng][2], acc[mi][ng][3]);
            }
        }
        __syncthreads();

        // ---- GATv2 epilogue: 8 edges per warp, fp16 gathers ----
#pragma unroll
        for (int e8 = 0; e8 < 8; e8++) {
            int el = wid * 8 + e8;
            int s = __shfl_sync(0xffffffffu, s_cur, e8);
            int d = __shfl_sync(0xffffffffu, d_cur, e8);

            float4 fe = *(const float4*)&sf[el * 132 + lane * 4];
            float4 fs = gather_h4(g_feat_src, s, lane);
            float4 fd = gather_h4(g_feat_dst, d, lane);

            float t0v = fs.x + fd.x + fe.x;
            float t1v = fs.y + fd.y + fe.y;
            float t2v = fs.z + fd.z + fe.z;
            float t3v = fs.w + fd.w + fe.w;
            float l0 = (t0v >= 0.f) ? t0v : NEG_SLOPE * t0v;
            float l1 = (t1v >= 0.f) ? t1v : NEG_SLOPE * t1v;
            float l2 = (t2v >= 0.f) ? t2v : NEG_SLOPE * t2v;
            float l3 = (t3v >= 0.f) ? t3v : NEG_SLOPE * t3v;

            float p = l0 * at.x + l1 * at.y + l2 * at.z + l3 * at.w;
            p += __shfl_xor_sync(0xffffffffu, p, 1);
            p += __shfl_xor_sync(0xffffffffu, p, 2);

            float ex = __expf(p);

            if ((lane & 3) == 0)
                atomicAdd(&g_z[(size_t)d * HEADS + (lane >> 2)], ex);

            float mx = (fs.x + fe.x) * ex;
            float my = (fs.y + fe.y) * ex;
            float mz = (fs.z + fe.z) * ex;
            float mw = (fs.w + fe.w) * ex;

            float* op = out + (size_t)d * FEAT + lane * 4;
            asm volatile("red.global.add.v4.f32 [%0], {%1,%2,%3,%4};"
                         :: "l"(op), "f"(mx), "f"(my), "f"(mz), "f"(mw)
                         : "memory");
        }
        __syncthreads();
    }
}

// ---------------- finalize out = relu(acc / z) --------------------------------
__global__ void finalize(float* __restrict__ out)
{
    int i = blockIdx.x * blockDim.x + threadIdx.x;
    if (i >= N_NODES * 32) return;
    int n = i >> 5;
    int q = i & 31;
    int h = q >> 2;
    float z = g_z[(size_t)n * HEADS + h];
    float inv = (z > 0.f) ? (1.f / z) : 0.f;
    float4 v = *(float4*)(out + (size_t)n * FEAT + q * 4);
    v.x = fmaxf(v.x * inv, 0.f);
    v.y = fmaxf(v.y * inv, 0.f);
    v.z = fmaxf(v.z * inv, 0.f);
    v.w = fmaxf(v.w * inv, 0.f);
    *(float4*)(out + (size_t)n * FEAT + q * 4) = v;
}

// ---------------- launch -----------------------------------------------------
extern "C" void kernel_launch(void* const* d_in, const int* in_sizes, int n_in,
                              void* d_out, int out_size)
{
    const float* x      = (const float*)d_in[0];
    const float* efeat  = (const float*)d_in[1];
    const int*   src    = (const int*)d_in[2];
    const int*   dst    = (const int*)d_in[3];
    const float* W_src  = (const float*)d_in[4];
    const float* b_src  = (const float*)d_in[5];
    const float* W_dst  = (const float*)d_in[6];
    const float* b_dst  = (const float*)d_in[7];
    const float* W_edge = (const float*)d_in[8];
    const float* attn   = (const float*)d_in[9];
    float* out = (float*)d_out;

    __half *p_fsrc = nullptr, *p_fdst = nullptr, *p_w = nullptr;
    cudaGetSymbolAddress((void**)&p_fsrc, g_feat_src);
    cudaGetSymbolAddress((void**)&p_fdst, g_feat_dst);
    cudaGetSymbolAddress((void**)&p_w, g_wsplit);

    cudaFuncSetAttribute(node_dual,
                         cudaFuncAttributeMaxDynamicSharedMemorySize, SMEM_N);
    cudaFuncSetAttribute(edge_persist,
                         cudaFuncAttributeMaxDynamicSharedMemorySize, SMEM_E);

    zero_kernel<<<(N_NODES * 32 + 255) / 256, 256>>>((float4*)out);
    prep_w<<<(3 * FEAT * FEAT + 255) / 256, 256>>>(W_src, W_dst, W_edge);

    const int WSZ = FEAT * FEAT;
    int nb_node = (N_NODES + 127) / 128;   // 391
    node_dual<<<nb_node, 256, SMEM_N>>>(
        x, p_w + 0 * WSZ, p_w + 1 * WSZ, b_src, p_fsrc,
           p_w + 2 * WSZ, p_w + 3 * WSZ, b_dst, p_fdst);

    edge_persist<<<GRID_P2, 256, SMEM_E>>>(
        efeat, p_w + 4 * WSZ, src, dst, attn, out);

    finalize<<<(N_NODES * 32 + 255) / 256, 256>>>(out);
}

// round 12
// speedup vs baseline: 3.8779x; 1.0837x over previous
#include <cuda_runtime.h>
#include <cuda_fp16.h>
#include <cstdint>
#include <cstddef>

#define N_NODES 50000
#define N_EDGES 800000
#define FEAT    128
#define HEADS   8
#define NEG_SLOPE 0.2f
#define NT3     6250        // 128-edge tiles
#define GRID_P2 296         // persistent CTAs (2 per SM)

typedef unsigned long long u64;
typedef unsigned int u32;

// ---------------- device scratch ---------------------------------------------
__device__ __half g_feat_src[(size_t)N_NODES * FEAT];   // 12.8 MB (fp16)
__device__ __half g_feat_dst[(size_t)N_NODES * FEAT];   // 12.8 MB (fp16)
__device__ float g_z[(size_t)N_NODES * HEADS];
__device__ __half g_wsplit[3 * 2 * FEAT * FEAT];

// ---------------- smem maps ---------------------------------------------------
#define PAD2    136
// node kernel (256 thr, 2 CTA/SM): full-K tiles
#define SA_N    0
#define SWH_N   34816
#define SWL_N   69632
#define SD_N    34816
#define SMEM_N  104448
// edge kernel (256 thr, 2 CTA/SM): 128-row A fp16, W fp16, D fp16
#define SA_E    0               // 128 x 136 fp16 = 34816
#define SW_E    34816           // 128 x 136 fp16 = 34816
#define SDH_E   69632           // 128 x 136 fp16 = 34816
#define SMEM_E  104448

// ---------------- helpers -----------------------------------------------------
__device__ __forceinline__ u32 smem_u32(const void* p) {
    u32 a;
    asm("{ .reg .u64 t; cvta.to.shared.u64 t, %1; cvt.u32.u64 %0, t; }"
        : "=r"(a) : "l"(p));
    return a;
}
__device__ __forceinline__ void ldsm4(u32& r0, u32& r1, u32& r2, u32& r3, u32 addr) {
    asm volatile("ldmatrix.sync.aligned.m8n8.x4.shared.b16 {%0,%1,%2,%3}, [%4];"
                 : "=r"(r0), "=r"(r1), "=r"(r2), "=r"(r3) : "r"(addr));
}
__device__ __forceinline__ void mma_f16(float* c, const u32* a, u32 b0, u32 b1) {
    asm volatile("mma.sync.aligned.m16n8k16.row.col.f32.f16.f16.f32 "
                 "{%0,%1,%2,%3}, {%4,%5,%6,%7}, {%8,%9}, {%0,%1,%2,%3};"
                 : "+f"(c[0]), "+f"(c[1]), "+f"(c[2]), "+f"(c[3])
                 : "r"(a[0]), "r"(a[1]), "r"(a[2]), "r"(a[3]), "r"(b0), "r"(b1));
}
__device__ __forceinline__ u64 cvt4_f16(float4 v) {
    u32 p01, p23;
    asm("cvt.rn.f16x2.f32 %0, %1, %2;" : "=r"(p01) : "f"(v.y), "f"(v.x));
    asm("cvt.rn.f16x2.f32 %0, %1, %2;" : "=r"(p23) : "f"(v.w), "f"(v.z));
    return (u64)p01 | ((u64)p23 << 32);
}
__device__ __forceinline__ u32 cvt2_f16(float a, float b) {
    u32 r;
    asm("cvt.rn.f16x2.f32 %0, %1, %2;" : "=r"(r) : "f"(b), "f"(a));
    return r;
}
__device__ __forceinline__ void cp_async16(u32 saddr, const void* gaddr) {
    asm volatile("cp.async.cg.shared.global [%0], [%1], 16;"
                 :: "r"(saddr), "l"(gaddr) : "memory");
}
__device__ __forceinline__ void cp_async_wait_all() {
    asm volatile("cp.async.commit_group;" ::: "memory");
    asm volatile("cp.async.wait_group 0;" ::: "memory");
}
__device__ __forceinline__ float4 h4_to_f4(uint2 hv) {
    __half2 h01 = *reinterpret_cast<__half2*>(&hv.x);
    __half2 h23 = *reinterpret_cast<__half2*>(&hv.y);
    float2 f01 = __half22float2(h01);
    float2 f23 = __half22float2(h23);
    return make_float4(f01.x, f01.y, f23.x, f23.y);
}
// gather 4 fp16 feats at [node*FEAT + lane*4] -> float4
__device__ __forceinline__ float4 gather_h4(const __half* base, int node, int lane) {
    uint2 hv = *(const uint2*)(base + (size_t)node * FEAT + lane * 4);
    return h4_to_f4(hv);
}
// streaming float4 load (evict-first)
__device__ __forceinline__ float4 ldcs4(const float* p) {
    float4 v;
    asm("ld.global.cs.v4.f32 {%0,%1,%2,%3}, [%4];"
        : "=f"(v.x), "=f"(v.y), "=f"(v.z), "=f"(v.w) : "l"(p));
    return v;
}

// ---------------- K0: zero ----------------------------------------------------
__global__ void zero_kernel(float4* __restrict__ out4)
{
    int i = blockIdx.x * blockDim.x + threadIdx.x;
    if (i < N_NODES * 32) out4[i] = make_float4(0.f, 0.f, 0.f, 0.f);
    if (i < N_NODES * HEADS / 4) ((float4*)g_z)[i] = make_float4(0.f, 0.f, 0.f, 0.f);
}

// ---------------- K-prep: weight fp16 hi/lo splits ----------------------------
__global__ void prep_w(const float* __restrict__ Ws, const float* __restrict__ Wd,
                       const float* __restrict__ We)
{
    int idx = blockIdx.x * blockDim.x + threadIdx.x;
    if (idx >= 3 * FEAT * FEAT) return;
    int w = idx / (FEAT * FEAT);
    int i = idx - w * (FEAT * FEAT);
    const float* srcp = (w == 0) ? Ws : (w == 1) ? Wd : We;
    float v = srcp[i];
    __half hi = __float2half_rn(v);
    __half lo = __float2half_rn(v - __half2float(hi));
    g_wsplit[(w * 2 + 0) * FEAT * FEAT + i] = hi;
    g_wsplit[(w * 2 + 1) * FEAT * FEAT + i] = lo;
}

// ================= node kernel: both projections, fp16 feat output ===========
__global__ __launch_bounds__(256, 2) void node_dual(
    const float* __restrict__ A,
    const __half* __restrict__ Wh1, const __half* __restrict__ Wl1,
    const float* __restrict__ b1, __half* __restrict__ C1,
    const __half* __restrict__ Wh2, const __half* __restrict__ Wl2,
    const float* __restrict__ b2, __half* __restrict__ C2)
{
    extern __shared__ char smem[];
    const u32 sbase = smem_u32(smem);
    float* sf = (float*)(smem + SD_N);
    const int tid = threadIdx.x;
    const int lane = tid & 31;
    const int wid = tid >> 5;
    const int warp_m = wid >> 1, warp_n = wid & 1;
    const int bm = blockIdx.x * 128;

    const int a_row = warp_m * 32 + ((lane >> 3) & 1) * 8 + (lane & 7);
    const int a_col = (lane >> 4) * 8;
    const u32 a_base = (u32)(a_row * PAD2 + a_col) * 2;
    const int b_row = warp_n * 64 + (lane >> 4) * 8 + (lane & 7);
    const int b_col = ((lane >> 3) & 1) * 8;
    const u32 b_base = (u32)(b_row * PAD2 + b_col) * 2;

    float acc[2][8][4];

    // load A (f32 -> fp16)
#pragma unroll
    for (int it = 0; it < 16; it++) {
        int idx = it * 256 + tid;
        int row = idx >> 5;
        int c4  = (idx & 31) << 2;
        float4 av = make_float4(0.f, 0.f, 0.f, 0.f);
        if (bm + row < N_NODES)
            av = *(const float4*)(A + (size_t)(bm + row) * FEAT + c4);
        *(u64*)(smem + SA_N + (u32)(row * PAD2 + c4) * 2) = cvt4_f16(av);
    }
    for (int pass = 0; pass < 2; pass++) {
        const __half* Wh = pass ? Wh2 : Wh1;
        const __half* Wl = pass ? Wl2 : Wl1;
#pragma unroll
        for (int it = 0; it < 8; it++) {
            int idx = it * 256 + tid;
            int row = idx >> 4;
            int c8  = (idx & 15) << 3;
            u32 soff = (u32)(row * PAD2 + c8) * 2;
            cp_async16(sbase + SWH_N + soff, Wh + (size_t)row * FEAT + c8);
            cp_async16(sbase + SWL_N + soff, Wl + (size_t)row * FEAT + c8);
        }
        cp_async_wait_all();
        __syncthreads();

#pragma unroll
        for (int mi = 0; mi < 2; mi++)
#pragma unroll
            for (int ng = 0; ng < 8; ng++)
#pragma unroll
                for (int j = 0; j < 4; j++) acc[mi][ng][j] = 0.0f;

#pragma unroll
        for (int ks = 0; ks < 8; ks++) {
            const u32 koff = (u32)ks * 32;
            u32 ah[2][4];
            ldsm4(ah[0][0], ah[0][1], ah[0][2], ah[0][3], sbase + SA_N + a_base + koff);
            ldsm4(ah[1][0], ah[1][1], ah[1][2], ah[1][3],
                  sbase + SA_N + a_base + (u32)(16 * PAD2) * 2 + koff);
#pragma unroll
            for (int p = 0; p < 4; p++) {
                const u32 poff = (u32)(p * 16 * PAD2) * 2 + koff;
                u32 bh[4], bl[4];
                ldsm4(bh[0], bh[1], bh[2], bh[3], sbase + SWH_N + b_base + poff);
                ldsm4(bl[0], bl[1], bl[2], bl[3], sbase + SWL_N + b_base + poff);
                int g0 = 2 * p, g1 = 2 * p + 1;
                mma_f16(acc[0][g0], ah[0], bh[0], bh[1]);
                mma_f16(acc[1][g0], ah[1], bh[0], bh[1]);
                mma_f16(acc[0][g1], ah[0], bh[2], bh[3]);
                mma_f16(acc[1][g1], ah[1], bh[2], bh[3]);
                mma_f16(acc[0][g0], ah[0], bl[0], bl[1]);
                mma_f16(acc[1][g0], ah[1], bl[0], bl[1]);
                mma_f16(acc[0][g1], ah[0], bl[2], bl[3]);
                mma_f16(acc[1][g1], ah[1], bl[2], bl[3]);
            }
        }
        __syncthreads();
        // stage D over W region
#pragma unroll
        for (int mi = 0; mi < 2; mi++) {
            int r0 = warp_m * 32 + mi * 16 + (lane >> 2);
            int cc = warp_n * 64 + (lane & 3) * 2;
#pragma unroll
            for (int ng = 0; ng < 8; ng++) {
                int col = cc + ng * 8;
                *(float2*)&sf[r0 * 132 + col] =
                    make_float2(acc[mi][ng][0], acc[mi][ng][1]);
                *(float2*)&sf[(r0 + 8) * 132 + col] =
                    make_float2(acc[mi][ng][2], acc[mi][ng][3]);
            }
        }
        __syncthreads();
        // store as fp16 (+bias)
        {
            const float* bias = pass ? b2 : b1;
            __half* C = pass ? C2 : C1;
            float4 b4 = *(const float4*)(bias + (tid & 31) * 4);
#pragma unroll 4
            for (int i = 0; i < 16; i++) {
                int row = i * 8 + (tid >> 5);
                int gr = bm + row;
                if (gr < N_NODES) {
                    float4 v = *(const float4*)&sf[row * 132 + (tid & 31) * 4];
                    v.x += b4.x; v.y += b4.y; v.z += b4.z; v.w += b4.w;
                    u64 hv = cvt4_f16(v);
                    *(u64*)(C + (size_t)gr * FEAT + (tid & 31) * 4) = hv;
                }
            }
        }
        __syncthreads();
    }
}

// ====== edge kernel: persistent, 128-edge tiles, 256 thr, 2 CTA/SM ==========
// Warp tile 32x64 (warp_m = wid>>1, warp_n = wid&1). D staged as fp16.
// Two barriers per tile: epilogue(t-1) and A-store(t) touch disjoint smem.
__global__ __launch_bounds__(256, 2) void edge_persist(
    const float* __restrict__ A,
    const __half* __restrict__ Wh,
    const int* __restrict__ src, const int* __restrict__ dst,
    const float* __restrict__ attn, float* __restrict__ out)
{
    extern __shared__ char smem[];
    const u32 sbase = smem_u32(smem);
    const int tid = threadIdx.x;
    const int lane = tid & 31;
    const int wid = tid >> 5;                      // 0..7
    const int warp_m = wid >> 1, warp_n = wid & 1; // 4x2 grid, 32x64 warp tiles

    // ---- W (fp16, single term) loaded ONCE per CTA ----
#pragma unroll
    for (int it = 0; it < 8; it++) {
        int idx = it * 256 + tid;                  // 0..2047 uint4
        int row = idx >> 4;
        int c8  = (idx & 15) << 3;
        cp_async16(sbase + SW_E + (u32)(row * PAD2 + c8) * 2,
                   Wh + (size_t)row * FEAT + c8);
    }
    cp_async_wait_all();

    const float4 at = *(const float4*)(attn + lane * 4);

    const int a_row = warp_m * 32 + ((lane >> 3) & 1) * 8 + (lane & 7);
    const int a_col = (lane >> 4) * 8;
    const u32 a_base = (u32)(a_row * PAD2 + a_col) * 2;
    const int b_row = warp_n * 64 + (lane >> 4) * 8 + (lane & 7);
    const int b_col = ((lane >> 3) & 1) * 8;
    const u32 b_base = (u32)(b_row * PAD2 + b_col) * 2;

    for (int t = blockIdx.x; t < NT3; t += GRID_P2) {
        // ---- load A(t): 128x128 f32 stream -> fp16 smem ----
#pragma unroll
        for (int it = 0; it < 16; it++) {
            int idx = it * 256 + tid;              // 0..4095 float4
            int row = idx >> 5;                    // 0..127
            int c4  = (idx & 31) << 2;
            float4 av = ldcs4(A + ((size_t)t * 128 + row) * FEAT + c4);
            *(u64*)(smem + SA_E + (u32)(row * PAD2 + c4) * 2) = cvt4_f16(av);
        }
        // indices for this warp's 16 edges (used after BAR2; latency hidden)
        int s_pre = 0, d_pre = 0;
        if (lane < 16) {
            s_pre = __ldg(src + t * 128 + wid * 16 + lane);
            d_pre = __ldg(dst + t * 128 + wid * 16 + lane);
        }
        __syncthreads();                           // BAR1: A ready, epi(t-1) done

        // ---- MMA: warp tile 32x64, fp16 W (single term) ----
        float acc[2][8][4];
#pragma unroll
        for (int mi = 0; mi < 2; mi++)
#pragma unroll
            for (int ng = 0; ng < 8; ng++)
#pragma unroll
                for (int j = 0; j < 4; j++) acc[mi][ng][j] = 0.0f;

#pragma unroll
        for (int ks = 0; ks < 8; ks++) {
            const u32 koff = (u32)ks * 32;
            u32 ah[2][4];
            ldsm4(ah[0][0], ah[0][1], ah[0][2], ah[0][3], sbase + SA_E + a_base + koff);
            ldsm4(ah[1][0], ah[1][1], ah[1][2], ah[1][3],
                  sbase + SA_E + a_base + (u32)(16 * PAD2) * 2 + koff);
#pragma unroll
            for (int p = 0; p < 4; p++) {
                const u32 poff = (u32)(p * 16 * PAD2) * 2 + koff;
                u32 bh[4];
                ldsm4(bh[0], bh[1], bh[2], bh[3], sbase + SW_E + b_base + poff);
                int g0 = 2 * p, g1 = 2 * p + 1;
                mma_f16(acc[0][g0], ah[0], bh[0], bh[1]);
                mma_f16(acc[1][g0], ah[1], bh[0], bh[1]);
                mma_f16(acc[0][g1], ah[0], bh[2], bh[3]);
                mma_f16(acc[1][g1], ah[1], bh[2], bh[3]);
            }
        }

        // ---- stage D as fp16 (128 x 136 halfs) ----
#pragma unroll
        for (int mi = 0; mi < 2; mi++) {
            int r0 = warp_m * 32 + mi * 16 + (lane >> 2);
            int cc = warp_n * 64 + (lane & 3) * 2;
#pragma unroll
            for (int ng = 0; ng < 8; ng++) {
                int col = cc + ng * 8;
                *(u32*)(smem + SDH_E + (u32)(r0 * PAD2 + col) * 2) =
                    cvt2_f16(acc[mi][ng][0], acc[mi][ng][1]);
                *(u32*)(smem + SDH_E + (u32)((r0 + 8) * PAD2 + col) * 2) =
                    cvt2_f16(acc[mi][ng][2], acc[mi][ng][3]);
            }
        }
        __syncthreads();                           // BAR2: D ready

        // ---- GATv2 epilogue: 16 edges per warp, fp16 D + fp16 gathers ----
#pragma unroll 4
        for (int e = 0; e < 16; e++) {
            int el = wid * 16 + e;
            int s = __shfl_sync(0xffffffffu, s_pre, e);
            int d = __shfl_sync(0xffffffffu, d_pre, e);

            uint2 fev = *(const uint2*)(smem + SDH_E + (u32)(el * PAD2 + lane * 4) * 2);
            float4 fe = h4_to_f4(fev);
            float4 fs = gather_h4(g_feat_src, s, lane);
            float4 fd = gather_h4(g_feat_dst, d, lane);

            float t0v = fs.x + fd.x + fe.x;
            float t1v = fs.y + fd.y + fe.y;
            float t2v = fs.z + fd.z + fe.z;
            float t3v = fs.w + fd.w + fe.w;
            float l0 = (t0v >= 0.f) ? t0v : NEG_SLOPE * t0v;
            float l1 = (t1v >= 0.f) ? t1v : NEG_SLOPE * t1v;
            float l2 = (t2v >= 0.f) ? t2v : NEG_SLOPE * t2v;
            float l3 = (t3v >= 0.f) ? t3v : NEG_SLOPE * t3v;

            float p = l0 * at.x + l1 * at.y + l2 * at.z + l3 * at.w;
            p += __shfl_xor_sync(0xffffffffu, p, 1);
            p += __shfl_xor_sync(0xffffffffu, p, 2);

            float ex = __expf(p);

            if ((lane & 3) == 0)
                atomicAdd(&g_z[(size_t)d * HEADS + (lane >> 2)], ex);

            float mx = (fs.x + fe.x) * ex;
            float my = (fs.y + fe.y) * ex;
            float mz = (fs.z + fe.z) * ex;
            float mw = (fs.w + fe.w) * ex;

            float* op = out + (size_t)d * FEAT + lane * 4;
            asm volatile("red.global.add.v4.f32 [%0], {%1,%2,%3,%4};"
                         :: "l"(op), "f"(mx), "f"(my), "f"(mz), "f"(mw)
                         : "memory");
        }
        // no trailing barrier: next A-store touches SA_E, disjoint from SDH_E
    }
}

// ---------------- finalize out = relu(acc / z) --------------------------------
__global__ void finalize(float* __restrict__ out)
{
    int i = blockIdx.x * blockDim.x + threadIdx.x;
    if (i >= N_NODES * 32) return;
    int n = i >> 5;
    int q = i & 31;
    int h = q >> 2;
    float z = g_z[(size_t)n * HEADS + h];
    float inv = (z > 0.f) ? (1.f / z) : 0.f;
    float4 v = *(float4*)(out + (size_t)n * FEAT + q * 4);
    v.x = fmaxf(v.x * inv, 0.f);
    v.y = fmaxf(v.y * inv, 0.f);
    v.z = fmaxf(v.z * inv, 0.f);
    v.w = fmaxf(v.w * inv, 0.f);
    *(float4*)(out + (size_t)n * FEAT + q * 4) = v;
}

// ---------------- launch -----------------------------------------------------
extern "C" void kernel_launch(void* const* d_in, const int* in_sizes, int n_in,
                              void* d_out, int out_size)
{
    const float* x      = (const float*)d_in[0];
    const float* efeat  = (const float*)d_in[1];
    const int*   src    = (const int*)d_in[2];
    const int*   dst    = (const int*)d_in[3];
    const float* W_src  = (const float*)d_in[4];
    const float* b_src  = (const float*)d_in[5];
    const float* W_dst  = (const float*)d_in[6];
    const float* b_dst  = (const float*)d_in[7];
    const float* W_edge = (const float*)d_in[8];
    const float* attn   = (const float*)d_in[9];
    float* out = (float*)d_out;

    __half *p_fsrc = nullptr, *p_fdst = nullptr, *p_w = nullptr;
    cudaGetSymbolAddress((void**)&p_fsrc, g_feat_src);
    cudaGetSymbolAddress((void**)&p_fdst, g_feat_dst);
    cudaGetSymbolAddress((void**)&p_w, g_wsplit);

    cudaFuncSetAttribute(node_dual,
                         cudaFuncAttributeMaxDynamicSharedMemorySize, SMEM_N);
    cudaFuncSetAttribute(edge_persist,
                         cudaFuncAttributeMaxDynamicSharedMemorySize, SMEM_E);

    zero_kernel<<<(N_NODES * 32 + 255) / 256, 256>>>((float4*)out);
    prep_w<<<(3 * FEAT * FEAT + 255) / 256, 256>>>(W_src, W_dst, W_edge);

    const int WSZ = FEAT * FEAT;
    int nb_node = (N_NODES + 127) / 128;   // 391
    node_dual<<<nb_node, 256, SMEM_N>>>(
        x, p_w + 0 * WSZ, p_w + 1 * WSZ, b_src, p_fsrc,
           p_w + 2 * WSZ, p_w + 3 * WSZ, b_dst, p_fdst);

    edge_persist<<<GRID_P2, 256, SMEM_E>>>(
        efeat, p_w + 4 * WSZ, src, dst, attn, out);

    finalize<<<(N_NODES * 32 + 255) / 256, 256>>>(out);
}

// round 13
// speedup vs baseline: 4.7055x; 1.2134x over previous
#include <cuda_runtime.h>
#include <cuda_fp16.h>
#include <cstdint>
#include <cstddef>

#define N_NODES 50000
#define N_EDGES 800000
#define FEAT    128
#define HEADS   8
#define NEG_SLOPE 0.2f
#define NT2     12500       // 64-edge tiles
#define GRID_P3 444         // persistent CTAs (3 per SM)

typedef unsigned long long u64;
typedef unsigned int u32;

// ---------------- device scratch ---------------------------------------------
__device__ __half g_feat_src[(size_t)N_NODES * FEAT];   // 12.8 MB (fp16)
__device__ __half g_feat_dst[(size_t)N_NODES * FEAT];   // 12.8 MB (fp16)
__device__ float g_z[(size_t)N_NODES * HEADS];
__device__ __half g_wsplit[3 * 2 * FEAT * FEAT];

// ---------------- smem maps ---------------------------------------------------
#define PAD2    136
// node kernel (256 thr, 2 CTA/SM): full-K tiles
#define SA_N    0
#define SWH_N   34816
#define SWL_N   69632
#define SD_N    34816
#define SMEM_N  104448
// edge kernel (256 thr, 3 CTA/SM): A/D overlay (64 x 136 fp16) + W fp16
#define SAD_E   0               // A during MMA, then D (fp16) after
#define SW_E    17408           // 128 x 136 fp16 = 34816
#define SMEM_E  52224

// ---------------- helpers -----------------------------------------------------
__device__ __forceinline__ u32 smem_u32(const void* p) {
    u32 a;
    asm("{ .reg .u64 t; cvta.to.shared.u64 t, %1; cvt.u32.u64 %0, t; }"
        : "=r"(a) : "l"(p));
    return a;
}
__device__ __forceinline__ void ldsm4(u32& r0, u32& r1, u32& r2, u32& r3, u32 addr) {
    asm volatile("ldmatrix.sync.aligned.m8n8.x4.shared.b16 {%0,%1,%2,%3}, [%4];"
                 : "=r"(r0), "=r"(r1), "=r"(r2), "=r"(r3) : "r"(addr));
}
__device__ __forceinline__ void mma_f16(float* c, const u32* a, u32 b0, u32 b1) {
    asm volatile("mma.sync.aligned.m16n8k16.row.col.f32.f16.f16.f32 "
                 "{%0,%1,%2,%3}, {%4,%5,%6,%7}, {%8,%9}, {%0,%1,%2,%3};"
                 : "+f"(c[0]), "+f"(c[1]), "+f"(c[2]), "+f"(c[3])
                 : "r"(a[0]), "r"(a[1]), "r"(a[2]), "r"(a[3]), "r"(b0), "r"(b1));
}
__device__ __forceinline__ u64 cvt4_f16(float4 v) {
    u32 p01, p23;
    asm("cvt.rn.f16x2.f32 %0, %1, %2;" : "=r"(p01) : "f"(v.y), "f"(v.x));
    asm("cvt.rn.f16x2.f32 %0, %1, %2;" : "=r"(p23) : "f"(v.w), "f"(v.z));
    return (u64)p01 | ((u64)p23 << 32);
}
__device__ __forceinline__ u32 cvt2_f16(float a, float b) {
    u32 r;
    asm("cvt.rn.f16x2.f32 %0, %1, %2;" : "=r"(r) : "f"(b), "f"(a));
    return r;
}
__device__ __forceinline__ void cp_async16(u32 saddr, const void* gaddr) {
    asm volatile("cp.async.cg.shared.global [%0], [%1], 16;"
                 :: "r"(saddr), "l"(gaddr) : "memory");
}
__device__ __forceinline__ void cp_async_wait_all() {
    asm volatile("cp.async.commit_group;" ::: "memory");
    asm volatile("cp.async.wait_group 0;" ::: "memory");
}
__device__ __forceinline__ float4 h4_to_f4(uint2 hv) {
    __half2 h01 = *reinterpret_cast<__half2*>(&hv.x);
    __half2 h23 = *reinterpret_cast<__half2*>(&hv.y);
    float2 f01 = __half22float2(h01);
    float2 f23 = __half22float2(h23);
    return make_float4(f01.x, f01.y, f23.x, f23.y);
}
__device__ __forceinline__ float4 gather_h4(const __half* base, int node, int lane) {
    uint2 hv = *(const uint2*)(base + (size_t)node * FEAT + lane * 4);
    return h4_to_f4(hv);
}
__device__ __forceinline__ float4 ldcs4(const float* p) {
    float4 v;
    asm("ld.global.cs.v4.f32 {%0,%1,%2,%3}, [%4];"
        : "=f"(v.x), "=f"(v.y), "=f"(v.z), "=f"(v.w) : "l"(p));
    return v;
}

// ---------------- K0: zero ----------------------------------------------------
__global__ void zero_kernel(float4* __restrict__ out4)
{
    int i = blockIdx.x * blockDim.x + threadIdx.x;
    if (i < N_NODES * 32) out4[i] = make_float4(0.f, 0.f, 0.f, 0.f);
    if (i < N_NODES * HEADS / 4) ((float4*)g_z)[i] = make_float4(0.f, 0.f, 0.f, 0.f);
}

// ---------------- K-prep: weight fp16 hi/lo splits ----------------------------
__global__ void prep_w(const float* __restrict__ Ws, const float* __restrict__ Wd,
                       const float* __restrict__ We)
{
    int idx = blockIdx.x * blockDim.x + threadIdx.x;
    if (idx >= 3 * FEAT * FEAT) return;
    int w = idx / (FEAT * FEAT);
    int i = idx - w * (FEAT * FEAT);
    const float* srcp = (w == 0) ? Ws : (w == 1) ? Wd : We;
    float v = srcp[i];
    __half hi = __float2half_rn(v);
    __half lo = __float2half_rn(v - __half2float(hi));
    g_wsplit[(w * 2 + 0) * FEAT * FEAT + i] = hi;
    g_wsplit[(w * 2 + 1) * FEAT * FEAT + i] = lo;
}

// ================= node kernel: both projections, fp16 feat output ===========
__global__ __launch_bounds__(256, 2) void node_dual(
    const float* __restrict__ A,
    const __half* __restrict__ Wh1, const __half* __restrict__ Wl1,
    const float* __restrict__ b1, __half* __restrict__ C1,
    const __half* __restrict__ Wh2, const __half* __restrict__ Wl2,
    const float* __restrict__ b2, __half* __restrict__ C2)
{
    extern __shared__ char smem[];
    const u32 sbase = smem_u32(smem);
    float* sf = (float*)(smem + SD_N);
    const int tid = threadIdx.x;
    const int lane = tid & 31;
    const int wid = tid >> 5;
    const int warp_m = wid >> 1, warp_n = wid & 1;
    const int bm = blockIdx.x * 128;

    const int a_row = warp_m * 32 + ((lane >> 3) & 1) * 8 + (lane & 7);
    const int a_col = (lane >> 4) * 8;
    const u32 a_base = (u32)(a_row * PAD2 + a_col) * 2;
    const int b_row = warp_n * 64 + (lane >> 4) * 8 + (lane & 7);
    const int b_col = ((lane >> 3) & 1) * 8;
    const u32 b_base = (u32)(b_row * PAD2 + b_col) * 2;

    float acc[2][8][4];

    // load A (f32 -> fp16)
#pragma unroll
    for (int it = 0; it < 16; it++) {
        int idx = it * 256 + tid;
        int row = idx >> 5;
        int c4  = (idx & 31) << 2;
        float4 av = make_float4(0.f, 0.f, 0.f, 0.f);
        if (bm + row < N_NODES)
            av = *(const float4*)(A + (size_t)(bm + row) * FEAT + c4);
        *(u64*)(smem + SA_N + (u32)(row * PAD2 + c4) * 2) = cvt4_f16(av);
    }
    for (int pass = 0; pass < 2; pass++) {
        const __half* Wh = pass ? Wh2 : Wh1;
        const __half* Wl = pass ? Wl2 : Wl1;
#pragma unroll
        for (int it = 0; it < 8; it++) {
            int idx = it * 256 + tid;
            int row = idx >> 4;
            int c8  = (idx & 15) << 3;
            u32 soff = (u32)(row * PAD2 + c8) * 2;
            cp_async16(sbase + SWH_N + soff, Wh + (size_t)row * FEAT + c8);
            cp_async16(sbase + SWL_N + soff, Wl + (size_t)row * FEAT + c8);
        }
        cp_async_wait_all();
        __syncthreads();

#pragma unroll
        for (int mi = 0; mi < 2; mi++)
#pragma unroll
            for (int ng = 0; ng < 8; ng++)
#pragma unroll
                for (int j = 0; j < 4; j++) acc[mi][ng][j] = 0.0f;

#pragma unroll
        for (int ks = 0; ks < 8; ks++) {
            const u32 koff = (u32)ks * 32;
            u32 ah[2][4];
            ldsm4(ah[0][0], ah[0][1], ah[0][2], ah[0][3], sbase + SA_N + a_base + koff);
            ldsm4(ah[1][0], ah[1][1], ah[1][2], ah[1][3],
                  sbase + SA_N + a_base + (u32)(16 * PAD2) * 2 + koff);
#pragma unroll
            for (int p = 0; p < 4; p++) {
                const u32 poff = (u32)(p * 16 * PAD2) * 2 + koff;
                u32 bh[4], bl[4];
                ldsm4(bh[0], bh[1], bh[2], bh[3], sbase + SWH_N + b_base + poff);
                ldsm4(bl[0], bl[1], bl[2], bl[3], sbase + SWL_N + b_base + poff);
                int g0 = 2 * p, g1 = 2 * p + 1;
                mma_f16(acc[0][g0], ah[0], bh[0], bh[1]);
                mma_f16(acc[1][g0], ah[1], bh[0], bh[1]);
                mma_f16(acc[0][g1], ah[0], bh[2], bh[3]);
                mma_f16(acc[1][g1], ah[1], bh[2], bh[3]);
                mma_f16(acc[0][g0], ah[0], bl[0], bl[1]);
                mma_f16(acc[1][g0], ah[1], bl[0], bl[1]);
                mma_f16(acc[0][g1], ah[0], bl[2], bl[3]);
                mma_f16(acc[1][g1], ah[1], bl[2], bl[3]);
            }
        }
        __syncthreads();
        // stage D over W region
#pragma unroll
        for (int mi = 0; mi < 2; mi++) {
            int r0 = warp_m * 32 + mi * 16 + (lane >> 2);
            int cc = warp_n * 64 + (lane & 3) * 2;
#pragma unroll
            for (int ng = 0; ng < 8; ng++) {
                int col = cc + ng * 8;
                *(float2*)&sf[r0 * 132 + col] =
                    make_float2(acc[mi][ng][0], acc[mi][ng][1]);
                *(float2*)&sf[(r0 + 8) * 132 + col] =
                    make_float2(acc[mi][ng][2], acc[mi][ng][3]);
            }
        }
        __syncthreads();
        // store as fp16 (+bias)
        {
            const float* bias = pass ? b2 : b1;
            __half* C = pass ? C2 : C1;
            float4 b4 = *(const float4*)(bias + (tid & 31) * 4);
#pragma unroll 4
            for (int i = 0; i < 16; i++) {
                int row = i * 8 + (tid >> 5);
                int gr = bm + row;
                if (gr < N_NODES) {
                    float4 v = *(const float4*)&sf[row * 132 + (tid & 31) * 4];
                    v.x += b4.x; v.y += b4.y; v.z += b4.z; v.w += b4.w;
                    u64 hv = cvt4_f16(v);
                    *(u64*)(C + (size_t)gr * FEAT + (tid & 31) * 4) = hv;
                }
            }
        }
        __syncthreads();
    }
}

// ====== edge kernel: persistent, 64-edge tiles, 256 thr, 3 CTA/SM ===========
// Warp tile 32x32 (2x4 warp grid). D (fp16) overlays the A region after MMA.
__global__ __launch_bounds__(256, 3) void edge_persist(
    const float* __restrict__ A,
    const __half* __restrict__ Wh,
    const int* __restrict__ src, const int* __restrict__ dst,
    const float* __restrict__ attn, float* __restrict__ out)
{
    extern __shared__ char smem[];
    const u32 sbase = smem_u32(smem);
    const int tid = threadIdx.x;
    const int lane = tid & 31;
    const int wid = tid >> 5;                      // 0..7
    const int warp_m = wid >> 2, warp_n = wid & 3; // 2x4 grid, 32x32 warp tiles

    // ---- W (fp16, single term) loaded ONCE per CTA ----
#pragma unroll
    for (int it = 0; it < 8; it++) {
        int idx = it * 256 + tid;                  // 0..2047 uint4
        int row = idx >> 4;
        int c8  = (idx & 15) << 3;
        cp_async16(sbase + SW_E + (u32)(row * PAD2 + c8) * 2,
                   Wh + (size_t)row * FEAT + c8);
    }
    cp_async_wait_all();
    __syncthreads();

    const float4 at = *(const float4*)(attn + lane * 4);

    const int a_row = warp_m * 32 + ((lane >> 3) & 1) * 8 + (lane & 7);
    const int a_col = (lane >> 4) * 8;
    const u32 a_base = (u32)(a_row * PAD2 + a_col) * 2;
    const int b_row = warp_n * 32 + (lane >> 4) * 8 + (lane & 7);
    const int b_col = ((lane >> 3) & 1) * 8;
    const u32 b_base = (u32)(b_row * PAD2 + b_col) * 2;

    for (int t = blockIdx.x; t < NT2; t += GRID_P3) {
        __syncthreads();                           // BAR0: epi(t-1) done reading D

        // ---- load A(t): 64x128 f32 stream -> fp16 smem (overlay region) ----
#pragma unroll
        for (int it = 0; it < 8; it++) {
            int idx = it * 256 + tid;              // 0..2047 float4
            int row = idx >> 5;                    // 0..63
            int c4  = (idx & 31) << 2;
            float4 av = ldcs4(A + ((size_t)t * 64 + row) * FEAT + c4);
            *(u64*)(smem + SAD_E + (u32)(row * PAD2 + c4) * 2) = cvt4_f16(av);
        }
        int s_pre = 0, d_pre = 0;
        if (lane < 8) {
            s_pre = __ldg(src + t * 64 + wid * 8 + lane);
            d_pre = __ldg(dst + t * 64 + wid * 8 + lane);
        }
        __syncthreads();                           // BAR1: A ready

        // ---- MMA: warp tile 32x32, fp16 W (single term) ----
        float acc[2][4][4];
#pragma unroll
        for (int mi = 0; mi < 2; mi++)
#pragma unroll
            for (int ng = 0; ng < 4; ng++)
#pragma unroll
                for (int j = 0; j < 4; j++) acc[mi][ng][j] = 0.0f;

#pragma unroll
        for (int ks = 0; ks < 8; ks++) {
            const u32 koff = (u32)ks * 32;
            u32 ah[2][4];
            ldsm4(ah[0][0], ah[0][1], ah[0][2], ah[0][3], sbase + SAD_E + a_base + koff);
            ldsm4(ah[1][0], ah[1][1], ah[1][2], ah[1][3],
                  sbase + SAD_E + a_base + (u32)(16 * PAD2) * 2 + koff);
#pragma unroll
            for (int p = 0; p < 2; p++) {
                const u32 poff = (u32)(p * 16 * PAD2) * 2 + koff;
                u32 bh[4];
                ldsm4(bh[0], bh[1], bh[2], bh[3], sbase + SW_E + b_base + poff);
                int g0 = 2 * p, g1 = 2 * p + 1;
                mma_f16(acc[0][g0], ah[0], bh[0], bh[1]);
                mma_f16(acc[1][g0], ah[1], bh[0], bh[1]);
                mma_f16(acc[0][g1], ah[0], bh[2], bh[3]);
                mma_f16(acc[1][g1], ah[1], bh[2], bh[3]);
            }
        }
        __syncthreads();                           // BAR2: all A reads retired

        // ---- stage D as fp16 over the A region ----
#pragma unroll
        for (int mi = 0; mi < 2; mi++) {
            int r0 = warp_m * 32 + mi * 16 + (lane >> 2);
            int cc = warp_n * 32 + (lane & 3) * 2;
#pragma unroll
            for (int ng = 0; ng < 4; ng++) {
                int col = cc + ng * 8;
                *(u32*)(smem + SAD_E + (u32)(r0 * PAD2 + col) * 2) =
                    cvt2_f16(acc[mi][ng][0], acc[mi][ng][1]);
                *(u32*)(smem + SAD_E + (u32)((r0 + 8) * PAD2 + col) * 2) =
                    cvt2_f16(acc[mi][ng][2], acc[mi][ng][3]);
            }
        }
        __syncthreads();                           // BAR3: D ready

        // ---- GATv2 epilogue: 8 edges per warp ----
#pragma unroll 4
        for (int e8 = 0; e8 < 8; e8++) {
            int el = wid * 8 + e8;
            int s = __shfl_sync(0xffffffffu, s_pre, e8);
            int d = __shfl_sync(0xffffffffu, d_pre, e8);

            uint2 fev = *(const uint2*)(smem + SAD_E + (u32)(el * PAD2 + lane * 4) * 2);
            float4 fe = h4_to_f4(fev);
            float4 fs = gather_h4(g_feat_src, s, lane);
            float4 fd = gather_h4(g_feat_dst, d, lane);

            float t0v = fs.x + fd.x + fe.x;
            float t1v = fs.y + fd.y + fe.y;
            float t2v = fs.z + fd.z + fe.z;
            float t3v = fs.w + fd.w + fe.w;
            float l0 = (t0v >= 0.f) ? t0v : NEG_SLOPE * t0v;
            float l1 = (t1v >= 0.f) ? t1v : NEG_SLOPE * t1v;
            float l2 = (t2v >= 0.f) ? t2v : NEG_SLOPE * t2v;
            float l3 = (t3v >= 0.f) ? t3v : NEG_SLOPE * t3v;

            float p = l0 * at.x + l1 * at.y + l2 * at.z + l3 * at.w;
            p += __shfl_xor_sync(0xffffffffu, p, 1);
            p += __shfl_xor_sync(0xffffffffu, p, 2);

            float ex = __expf(p);

            if ((lane & 3) == 0)
                atomicAdd(&g_z[(size_t)d * HEADS + (lane >> 2)], ex);

            float mx = (fs.x + fe.x) * ex;
            float my = (fs.y + fe.y) * ex;
            float mz = (fs.z + fe.z) * ex;
            float mw = (fs.w + fe.w) * ex;

            float* op = out + (size_t)d * FEAT + lane * 4;
            asm volatile("red.global.add.v4.f32 [%0], {%1,%2,%3,%4};"
                         :: "l"(op), "f"(mx), "f"(my), "f"(mz), "f"(mw)
                         : "memory");
        }
    }
}

// ---------------- finalize out = relu(acc / z) --------------------------------
__global__ void finalize(float* __restrict__ out)
{
    int i = blockIdx.x * blockDim.x + threadIdx.x;
    if (i >= N_NODES * 32) return;
    int n = i >> 5;
    int q = i & 31;
    int h = q >> 2;
    float z = g_z[(size_t)n * HEADS + h];
    float inv = (z > 0.f) ? (1.f / z) : 0.f;
    float4 v = *(float4*)(out + (size_t)n * FEAT + q * 4);
    v.x = fmaxf(v.x * inv, 0.f);
    v.y = fmaxf(v.y * inv, 0.f);
    v.z = fmaxf(v.z * inv, 0.f);
    v.w = fmaxf(v.w * inv, 0.f);
    *(float4*)(out + (size_t)n * FEAT + q * 4) = v;
}

// ---------------- launch -----------------------------------------------------
extern "C" void kernel_launch(void* const* d_in, const int* in_sizes, int n_in,
                              void* d_out, int out_size)
{
    const float* x      = (const float*)d_in[0];
    const float* efeat  = (const float*)d_in[1];
    const int*   src    = (const int*)d_in[2];
    const int*   dst    = (const int*)d_in[3];
    const float* W_src  = (const float*)d_in[4];
    const float* b_src  = (const float*)d_in[5];
    const float* W_dst  = (const float*)d_in[6];
    const float* b_dst  = (const float*)d_in[7];
    const float* W_edge = (const float*)d_in[8];
    const float* attn   = (const float*)d_in[9];
    float* out = (float*)d_out;

    __half *p_fsrc = nullptr, *p_fdst = nullptr, *p_w = nullptr;
    cudaGetSymbolAddress((void**)&p_fsrc, g_feat_src);
    cudaGetSymbolAddress((void**)&p_fdst, g_feat_dst);
    cudaGetSymbolAddress((void**)&p_w, g_wsplit);

    cudaFuncSetAttribute(node_dual,
                         cudaFuncAttributeMaxDynamicSharedMemorySize, SMEM_N);
    cudaFuncSetAttribute(edge_persist,
                         cudaFuncAttributeMaxDynamicSharedMemorySize, SMEM_E);

    zero_kernel<<<(N_NODES * 32 + 255) / 256, 256>>>((float4*)out);
    prep_w<<<(3 * FEAT * FEAT + 255) / 256, 256>>>(W_src, W_dst, W_edge);

    const int WSZ = FEAT * FEAT;
    int nb_node = (N_NODES + 127) / 128;   // 391
    node_dual<<<nb_node, 256, SMEM_N>>>(
        x, p_w + 0 * WSZ, p_w + 1 * WSZ, b_src, p_fsrc,
           p_w + 2 * WSZ, p_w + 3 * WSZ, b_dst, p_fdst);

    edge_persist<<<GRID_P3, 256, SMEM_E>>>(
        efeat, p_w + 4 * WSZ, src, dst, attn, out);

    finalize<<<(N_NODES * 32 + 255) / 256, 256>>>(out);
}